// round 14
// baseline (speedup 1.0000x reference)
#include <cuda_runtime.h>
#include <cuda_bf16.h>

typedef __nv_bfloat16 bf16;

// ---------------- problem constants ----------------
#define BATCH   64
#define T_VID   40
#define D_VID   2048
#define HDIM    1024
#define WDIM    512
#define VOCAB   32000
#define MAXLEN  28
#define DECSTEPS (MAXLEN-1)          // 27
#define NSTEPS  (T_VID + DECSTEPS)   // 67
#define G3      (3*HDIM)             // 3072
#define MROWS   (DECSTEPS*BATCH)     // 1728

// ---------------- big-GEMM tiling (proven R7: 64 x 256, BK=64, 2-stage) ----------------
#define SKEW 8
#define SSTRIDE (64+SKEW)            // 72
#define ASZ (64*SSTRIDE)             // 4608
#define SM_G256 ((2*ASZ + 2*256*SSTRIDE)*2)  // 92160

// ---------------- recurrence tiling: full-K resident block, quartered bulk loader ----------------
#define RBLK 64                      // recurrence CTAs (16 h-cols each)
#define RSTRIDE 1032                 // 1024 + 8 skew elems; row pitch 2064 B (16B-aligned)
#define RA_ROWS 64
#define RB_ROWS 48
#define SM_REC ((RA_ROWS+RB_ROWS)*RSTRIDE*2)   // 231168 bytes
#define QBYTES ((RA_ROWS+RB_ROWS)*512u)        // 57344 bytes per K-quarter

// ---------------- device scratch ----------------
__device__ bf16  g_Wih1[(size_t)G3*D_VID];
__device__ bf16  g_Whh1[(size_t)G3*HDIM];
__device__ bf16  g_Wih2[(size_t)G3*(HDIM+WDIM)];
__device__ bf16  g_Whh2[(size_t)G3*HDIM];
__device__ bf16  g_Wout[(size_t)VOCAB*HDIM];
__device__ bf16  g_vid [(size_t)T_VID*BATCH*D_VID];
__device__ bf16  g_words[(size_t)MROWS*WDIM];
__device__ float g_GI1 [(size_t)T_VID*BATCH*G3];
__device__ float g_GI2w[(size_t)MROWS*G3];
__device__ float g_h1  [(size_t)BATCH*HDIM];
__device__ float g_h2  [(size_t)BATCH*HDIM];
__device__ bf16  g_h1b [2*(size_t)BATCH*HDIM];   // double-buffered bf16 copies
__device__ bf16  g_h2b [2*(size_t)BATCH*HDIM];
__device__ bf16  g_H2all[(size_t)MROWS*HDIM];

// barrier state (sense-reversing, survives graph replays)
__device__ unsigned g_bar_count = 0;
__device__ volatile unsigned g_bar_sense = 0;

// ---------------- helpers ----------------
__device__ __forceinline__ void cp16(void* s, const void* g) {
    unsigned sa = (unsigned)__cvta_generic_to_shared(s);
    asm volatile("cp.async.cg.shared.global [%0], [%1], 16;\n" :: "r"(sa), "l"(g));
}
__device__ __forceinline__ void cp_commit() {
    asm volatile("cp.async.commit_group;\n" ::: "memory");
}
__device__ __forceinline__ void cp_wait0() {
    asm volatile("cp.async.wait_group 0;\n" ::: "memory");
}
__device__ __forceinline__ void mma16816(float* c, const unsigned* a, const unsigned* b) {
    asm volatile(
        "mma.sync.aligned.m16n8k16.row.col.f32.bf16.bf16.f32 "
        "{%0,%1,%2,%3}, {%4,%5,%6,%7}, {%8,%9}, {%0,%1,%2,%3};\n"
        : "+f"(c[0]), "+f"(c[1]), "+f"(c[2]), "+f"(c[3])
        : "r"(a[0]), "r"(a[1]), "r"(a[2]), "r"(a[3]), "r"(b[0]), "r"(b[1]));
}
__device__ __forceinline__ float sigmf(float x) { return 1.f / (1.f + expf(-x)); }

// bulk async copy global->shared with mbarrier transaction completion
__device__ __forceinline__ void bulk_cp(unsigned dst_smem, const void* src, unsigned bytes,
                                        unsigned mbar) {
    asm volatile(
        "cp.async.bulk.shared::cluster.global.mbarrier::complete_tx::bytes [%0], [%1], %2, [%3];"
        :: "r"(dst_smem), "l"(src), "r"(bytes), "r"(mbar) : "memory");
}
__device__ __forceinline__ void mbar_init(unsigned mbar, unsigned count) {
    asm volatile("mbarrier.init.shared.b64 [%0], %1;" :: "r"(mbar), "r"(count) : "memory");
}
__device__ __forceinline__ void mbar_expect_tx(unsigned mbar, unsigned bytes) {
    asm volatile("mbarrier.arrive.expect_tx.shared.b64 _, [%0], %1;"
                 :: "r"(mbar), "r"(bytes) : "memory");
}
__device__ __forceinline__ void mbar_wait(unsigned mbar, unsigned parity) {
    asm volatile(
        "{\n\t"
        ".reg .pred P1;\n\t"
        "WAIT_LOOP_%=:\n\t"
        "mbarrier.try_wait.parity.acquire.cta.shared::cta.b64 P1, [%0], %1, 0x989680;\n\t"
        "@P1 bra.uni WAIT_DONE_%=;\n\t"
        "bra.uni WAIT_LOOP_%=;\n\t"
        "WAIT_DONE_%=:\n\t"
        "}"
        :: "r"(mbar), "r"(parity) : "memory");
}

// ==================== proven big GEMM (R7 + 2 CTAs/SM): C = A @ B^T (+bias) ====================
template<int TBN>
__global__ void __launch_bounds__(256, 2)
gemm_kernel(const bf16* __restrict__ A, int lda,
            const bf16* __restrict__ B, int ldb,
            float* __restrict__ C, int ldc,
            const float* __restrict__ bias,
            int K, int permute_out)
{
    constexpr int NI   = TBN / 32;
    constexpr int BSZT = TBN * SSTRIDE;

    extern __shared__ bf16 smem[];
    bf16* sA = smem;
    bf16* sB = smem + 2*ASZ;

    const int tid  = threadIdx.x;
    const int lane = tid & 31;
    const int warp = tid >> 5;
    const int wm   = warp & 1;
    const int wn   = warp >> 1;
    const int bm   = blockIdx.y * 64;
    const int bn   = blockIdx.x * TBN;

    float acc[2][NI][4];
#pragma unroll
    for (int mi = 0; mi < 2; mi++)
#pragma unroll
        for (int ni = 0; ni < NI; ni++)
#pragma unroll
            for (int q = 0; q < 4; q++) acc[mi][ni][q] = 0.f;

    const int KT = K >> 6;

    auto issue_stage = [&](int st, int kt) {
        const int k0 = kt << 6;
#pragma unroll
        for (int i = 0; i < 2; i++) {
            int ch = tid + (i << 8);
            int r = ch >> 3, c = (ch & 7) << 3;
            cp16(&sA[st*ASZ + r*SSTRIDE + c], A + (size_t)(bm + r)*lda + k0 + c);
        }
#pragma unroll
        for (int i = 0; i < NI; i++) {
            int ch = tid + (i << 8);
            int r = ch >> 3, c = (ch & 7) << 3;
            cp16(&sB[st*BSZT + r*SSTRIDE + c], B + (size_t)(bn + r)*ldb + k0 + c);
        }
        cp_commit();
    };

    issue_stage(0, 0);

    for (int kt = 0; kt < KT; kt++) {
        cp_wait0();
        __syncthreads();
        if (kt + 1 < KT) issue_stage((kt + 1) & 1, kt + 1);

        const bf16* a = sA + (kt & 1) * ASZ;
        const bf16* b = sB + (kt & 1) * BSZT;

#pragma unroll
        for (int kk = 0; kk < 4; kk++) {
            const int kc = kk * 16 + ((lane & 3) << 1);
            unsigned af[2][4];
#pragma unroll
            for (int mi = 0; mi < 2; mi++) {
                int r = wm * 32 + mi * 16 + (lane >> 2);
                af[mi][0] = *(const unsigned*)(a + (size_t)r * SSTRIDE + kc);
                af[mi][1] = *(const unsigned*)(a + (size_t)(r + 8) * SSTRIDE + kc);
                af[mi][2] = *(const unsigned*)(a + (size_t)r * SSTRIDE + kc + 8);
                af[mi][3] = *(const unsigned*)(a + (size_t)(r + 8) * SSTRIDE + kc + 8);
            }
            unsigned bfr[NI][2];
#pragma unroll
            for (int ni = 0; ni < NI; ni++) {
                int r = wn * (TBN/4) + ni * 8 + (lane >> 2);
                bfr[ni][0] = *(const unsigned*)(b + (size_t)r * SSTRIDE + kc);
                bfr[ni][1] = *(const unsigned*)(b + (size_t)r * SSTRIDE + kc + 8);
            }
#pragma unroll
            for (int mi = 0; mi < 2; mi++)
#pragma unroll
                for (int ni = 0; ni < NI; ni++)
                    mma16816(acc[mi][ni], af[mi], bfr[ni]);
        }
        __syncthreads();
    }

#pragma unroll
    for (int mi = 0; mi < 2; mi++) {
#pragma unroll
        for (int ni = 0; ni < NI; ni++) {
            int r0 = wm * 32 + mi * 16 + (lane >> 2);
            int c0 = bn + wn * (TBN/4) + ni * 8 + ((lane & 3) << 1);
#pragma unroll
            for (int p = 0; p < 2; p++) {
                int row = bm + r0 + p * 8;
                float x0 = acc[mi][ni][p * 2 + 0];
                float x1 = acc[mi][ni][p * 2 + 1];
                if (bias) { x0 += __ldg(bias + c0); x1 += __ldg(bias + c0 + 1); }
                size_t orow = permute_out ? (size_t)((row & 63) * DECSTEPS + (row >> 6))
                                          : (size_t)row;
                *(float2*)(C + orow * (size_t)ldc + c0) = make_float2(x0, x1);
            }
        }
    }
}

// ==================== persistent recurrence megakernel (quartered bulk loader) ====================
// 64 CTAs x 256 threads. CTA c owns h columns [16c, 16c+16).
// Per step: block gh1 | gate1 | block gh2 | gsync | block gi2 | gate2 | gsync.
// Each block loads A(64x1024) + B(48x1024) as 4 K-quarter transactions (4 mbarriers,
// 112 x 512B bulk copies per quarter), then wait-q/compute-q overlapped:
// quarter q's MMA runs while quarters q+1..3 are still in flight.
// Single smem allocation per block; expect_tx -> __syncthreads -> issue -> monotone waits.
__global__ void __launch_bounds__(256, 1)
recurrence_kernel(const bf16* __restrict__ Whh1,
                  const bf16* __restrict__ Wih2,
                  const bf16* __restrict__ Whh2,
                  const float* __restrict__ bih1,
                  const float* __restrict__ bhh1,
                  const float* __restrict__ bih2,
                  const float* __restrict__ bhh2,
                  const float* __restrict__ GI1,
                  const float* __restrict__ GI2w,
                  float* h1, float* h2, bf16* h1bb, bf16* h2bb, bf16* H2all)
{
    extern __shared__ bf16 smem[];
    __shared__ __align__(8) unsigned long long s_mbar[4];
    const int cid  = blockIdx.x;
    const int tid  = threadIdx.x;
    const int lane = tid & 31;
    const int warp = tid >> 5;
    const int wm   = warp & 3;       // 4 row-groups of 16
    const int wn   = warp >> 2;      // 2 col-halves of 8

    const unsigned smem_b = (unsigned)__cvta_generic_to_shared(smem);
    const unsigned mbar0  = (unsigned)__cvta_generic_to_shared(&s_mbar[0]);
    int bphase = 0;                  // phase parity for all 4 barriers (flips per block)

    __shared__ unsigned s_sense;
    if (tid == 0) {
        s_sense = g_bar_sense;
#pragma unroll
        for (int q = 0; q < 4; q++) mbar_init(mbar0 + q * 8, 1);
    }
    __syncthreads();

    auto gsync = [&]() {
        __syncthreads();
        if (tid == 0) {
            unsigned ls = s_sense ^ 1u;
            s_sense = ls;
            __threadfence();
            if (atomicAdd(&g_bar_count, 1u) == RBLK - 1) {
                atomicExch(&g_bar_count, 0u);
                __threadfence();
                g_bar_sense = ls;
            } else {
                while (g_bar_sense != ls) __nanosleep(32);
            }
        }
        __syncthreads();
    };

    // MMA over one quarter (16 k-chunks of 16): 3 gate accumulators.
    auto mmq = [&](int q, float* aR, float* aZ, float* aN) {
        const bf16* a = smem;
        const bf16* b = smem + (size_t)RA_ROWS * RSTRIDE;
#pragma unroll
        for (int kk2 = 0; kk2 < 16; kk2++) {
            const int kk = (q << 4) + kk2;
            const int kc = (kk << 4) + ((lane & 3) << 1);
            unsigned af[4];
            int r = (wm << 4) + (lane >> 2);
            af[0] = *(const unsigned*)(a + (size_t)r * RSTRIDE + kc);
            af[1] = *(const unsigned*)(a + (size_t)(r + 8) * RSTRIDE + kc);
            af[2] = *(const unsigned*)(a + (size_t)r * RSTRIDE + kc + 8);
            af[3] = *(const unsigned*)(a + (size_t)(r + 8) * RSTRIDE + kc + 8);
            int b0r = (wn << 3) + (lane >> 2);
            {
                unsigned bb[2] = { *(const unsigned*)(b + (size_t)b0r * RSTRIDE + kc),
                                   *(const unsigned*)(b + (size_t)b0r * RSTRIDE + kc + 8) };
                mma16816(aR, af, bb);
            }
            {
                int br = 16 + b0r;
                unsigned bb[2] = { *(const unsigned*)(b + (size_t)br * RSTRIDE + kc),
                                   *(const unsigned*)(b + (size_t)br * RSTRIDE + kc + 8) };
                mma16816(aZ, af, bb);
            }
            {
                int br = 32 + b0r;
                unsigned bb[2] = { *(const unsigned*)(b + (size_t)br * RSTRIDE + kc),
                                   *(const unsigned*)(b + (size_t)br * RSTRIDE + kc + 8) };
                mma16816(aN, af, bb);
            }
        }
    };

    // full block: 4 quartered bulk transactions; overlap wait-q with compute of q-1.
    auto block_gemm = [&](const bf16* Asrc, const bf16* Bsrc, int ldb,
                          float* aR, float* aZ, float* aN) {
        if (tid == 0) {
#pragma unroll
            for (int q = 0; q < 4; q++) mbar_expect_tx(mbar0 + q * 8, QBYTES);
        }
        __syncthreads();   // expect_tx set AND all threads done reading previous block
        if (tid < RA_ROWS) {
            const bf16* src = Asrc + (size_t)tid * HDIM;
            unsigned dst = smem_b + tid * (RSTRIDE * 2);
#pragma unroll
            for (int q = 0; q < 4; q++)
                bulk_cp(dst + q * 512, src + q * 256, 512, mbar0 + q * 8);
        } else if (tid < RA_ROWS + RB_ROWS) {
            int br = tid - RA_ROWS;
            int grow = (br >> 4) * HDIM + (cid << 4) + (br & 15);
            const bf16* src = Bsrc + (size_t)grow * ldb;
            unsigned dst = smem_b + (RA_ROWS + br) * (RSTRIDE * 2);
#pragma unroll
            for (int q = 0; q < 4; q++)
                bulk_cp(dst + q * 512, src + q * 256, 512, mbar0 + q * 8);
        }
#pragma unroll
        for (int q = 0; q < 4; q++) {
            mbar_wait(mbar0 + q * 8, (unsigned)bphase);
            mmq(q, aR, aZ, aN);
        }
        bphase ^= 1;
    };

    // ---- zero initial state (fp32 + bf16 buffer 0) ----
    for (int i = cid * 256 + tid; i < BATCH * HDIM; i += RBLK * 256) {
        __stcg(h1 + i, 0.f);
        __stcg(h2 + i, 0.f);
        __stcg((unsigned short*)h1bb + i, (unsigned short)0);
        __stcg((unsigned short*)h2bb + i, (unsigned short)0);
    }
    gsync();

    for (int t = 0; t < NSTEPS; t++) {
        const bool enc = (t < T_VID);
        const int p = t & 1;
        const bf16* h1r = h1bb + (size_t)p       * BATCH * HDIM;   // read buffer
        bf16*       h1w = h1bb + (size_t)(p ^ 1) * BATCH * HDIM;   // write buffer
        const bf16* h2r = h2bb + (size_t)p       * BATCH * HDIM;
        bf16*       h2w = h2bb + (size_t)(p ^ 1) * BATCH * HDIM;

        // ---- block 1: gh1 = h1r @ Whh1^T ----
        float aR1[4] = {0,0,0,0}, aZ1[4] = {0,0,0,0}, aN1[4] = {0,0,0,0};
        block_gemm(h1r, Whh1, HDIM, aR1, aZ1, aN1);

        // ---- gate1 epilogue -> h1 (fp32), h1w (bf16) ----
        {
            const float* git = enc ? (GI1 + (size_t)t * BATCH * G3) : bih1;
            const int gstride = enc ? G3 : 0;
#pragma unroll
            for (int pp = 0; pp < 2; pp++) {
#pragma unroll
                for (int q = 0; q < 2; q++) {
                    int row = (wm << 4) + (lane >> 2) + (pp << 3);
                    int j = (cid << 4) + (wn << 3) + ((lane & 3) << 1) + q;
                    int idx = (pp << 1) + q;
                    const float* gp = git + (size_t)row * gstride;
                    float rr = sigmf(gp[j]          + aR1[idx] + __ldg(bhh1 + j));
                    float zz = sigmf(gp[j + HDIM]   + aZ1[idx] + __ldg(bhh1 + j + HDIM));
                    float nn = tanhf(gp[j + 2*HDIM] + rr * (aN1[idx] + __ldg(bhh1 + j + 2*HDIM)));
                    int o = row * HDIM + j;
                    float hv = (1.f - zz) * nn + zz * __ldcg(h1 + o);
                    __stcg(h1 + o, hv);
                    __stcg((unsigned short*)h1w + o,
                           __bfloat16_as_ushort(__float2bfloat16(hv)));
                }
            }
        }

        // ---- block 2: gh2 = h2r @ Whh2^T (independent of gate1; pre-barrier) ----
        float aR2[4] = {0,0,0,0}, aZ2[4] = {0,0,0,0}, aNh[4] = {0,0,0,0};
        block_gemm(h2r, Whh2, HDIM, aR2, aZ2, aNh);
        gsync();   // all h1w writes complete chip-wide

        // ---- block 3: gi2 = h1w @ Wih2[:, :H]^T ----
        float aRi[4] = {0,0,0,0}, aZi[4] = {0,0,0,0}, aNi[4] = {0,0,0,0};
        block_gemm(h1w, Wih2, HDIM + WDIM, aRi, aZi, aNi);

        // ---- gate2 epilogue (combines block 2 + block 3 accumulators) ----
        {
            const int td = t - T_VID;
            bf16* h2save = enc ? nullptr : (H2all + (size_t)td * BATCH * HDIM);
#pragma unroll
            for (int pp = 0; pp < 2; pp++) {
#pragma unroll
                for (int q = 0; q < 2; q++) {
                    int row = (wm << 4) + (lane >> 2) + (pp << 3);
                    int j = (cid << 4) + (wn << 3) + ((lane & 3) << 1) + q;
                    int idx = (pp << 1) + q;
                    float wr = 0.f, wz = 0.f, wn_ = 0.f;
                    if (!enc) {
                        const float* w = GI2w + ((size_t)td * BATCH + row) * G3;
                        wr  = __ldcg(w + j);
                        wz  = __ldcg(w + j + HDIM);
                        wn_ = __ldcg(w + j + 2*HDIM);
                    }
                    float rr = sigmf(aRi[idx] + aR2[idx] + __ldg(bih2 + j) + __ldg(bhh2 + j) + wr);
                    float zz = sigmf(aZi[idx] + aZ2[idx] + __ldg(bih2 + j + HDIM) + __ldg(bhh2 + j + HDIM) + wz);
                    float nn = tanhf(aNi[idx] + __ldg(bih2 + j + 2*HDIM) + wn_
                                     + rr * (aNh[idx] + __ldg(bhh2 + j + 2*HDIM)));
                    int o = row * HDIM + j;
                    float hv = (1.f - zz) * nn + zz * __ldcg(h2 + o);
                    __stcg(h2 + o, hv);
                    unsigned short us = __bfloat16_as_ushort(__float2bfloat16(hv));
                    __stcg((unsigned short*)h2w + o, us);
                    if (h2save) __stcg((unsigned short*)h2save + o, us);
                }
            }
        }
        gsync();
    }
}

// ---------------- fused prep: 5 weight conversions + vid permute + word gather ----------------
#define CN1 ((long)G3*D_VID/2)
#define CN2 ((long)G3*HDIM/2)
#define CN3 ((long)G3*(HDIM+WDIM)/2)
#define CN4 ((long)G3*HDIM/2)
#define CN5 ((long)VOCAB*HDIM/2)
#define CNW (CN1+CN2+CN3+CN4+CN5)
#define PN_VID ((long)T_VID*BATCH*(D_VID/2))
#define PN_WRD ((long)MROWS*(WDIM/2))
__global__ void prep_kernel(const float* __restrict__ a1, bf16* o1,
                            const float* __restrict__ a2, bf16* o2,
                            const float* __restrict__ a3, bf16* o3,
                            const float* __restrict__ a4, bf16* o4,
                            const float* __restrict__ a5, bf16* o5,
                            const float* __restrict__ vid, bf16* __restrict__ vout,
                            const int* __restrict__ tgt, const float* __restrict__ emb,
                            bf16* __restrict__ wout)
{
    const long total = CNW + PN_VID + PN_WRD;
    long i = blockIdx.x * 256L + threadIdx.x;
    long stride = (long)gridDim.x * 256;
    for (; i < total; i += stride) {
        if (i < CNW) {
            const float2* src; __nv_bfloat162* dst; long j = i;
            if (j < CN1) { src = (const float2*)a1; dst = (__nv_bfloat162*)o1; }
            else if ((j -= CN1) < CN2) { src = (const float2*)a2; dst = (__nv_bfloat162*)o2; }
            else if ((j -= CN2) < CN3) { src = (const float2*)a3; dst = (__nv_bfloat162*)o3; }
            else if ((j -= CN3) < CN4) { src = (const float2*)a4; dst = (__nv_bfloat162*)o4; }
            else { j -= CN4; src = (const float2*)a5; dst = (__nv_bfloat162*)o5; }
            dst[j] = __float22bfloat162_rn(src[j]);
        } else if (i < CNW + PN_VID) {
            long k = i - CNW;
            long d2 = k & (D_VID/2 - 1);
            long tb = k >> 10;
            long b = tb & 63, t = tb >> 6;
            float2 v = ((const float2*)vid)[((b * T_VID + t) << 10) + d2];
            ((__nv_bfloat162*)vout)[k] = __float22bfloat162_rn(v);
        } else {
            long k = i - CNW - PN_VID;
            long j2 = k & (WDIM/2 - 1);
            long tb = k >> 8;
            long b = tb & 63, t = tb >> 6;
            int tok = tgt[b * MAXLEN + t];
            float2 v = ((const float2*)emb)[(long)tok * (WDIM/2) + j2];
            ((__nv_bfloat162*)wout)[k] = __float22bfloat162_rn(v);
        }
    }
}

// ---------------- online 2-pass log_softmax (rows of 32000 fp32) ----------------
__global__ void logsoftmax_kernel(float* __restrict__ data) {
    const int n4 = VOCAB / 4;
    float* row = data + (size_t)blockIdx.x * VOCAB;
    float4* r4 = (float4*)row;
    const int tid = threadIdx.x;
    const int lane = tid & 31, warp = tid >> 5;
    __shared__ float sm[8], ss[8];

    float m = -3.4e38f, s = 0.f;
    for (int i = tid; i < n4; i += 256) {
        float4 v = r4[i];
        float vv[4] = {v.x, v.y, v.z, v.w};
#pragma unroll
        for (int k = 0; k < 4; k++) {
            float x = vv[k];
            if (x > m) { s = s * __expf(m - x) + 1.f; m = x; }
            else         s += __expf(x - m);
        }
    }
#pragma unroll
    for (int o = 16; o; o >>= 1) {
        float om = __shfl_xor_sync(~0u, m, o);
        float os = __shfl_xor_sync(~0u, s, o);
        float nm = fmaxf(m, om);
        s = s * __expf(m - nm) + os * __expf(om - nm);
        m = nm;
    }
    if (lane == 0) { sm[warp] = m; ss[warp] = s; }
    __syncthreads();
    float M = sm[0], S = ss[0];
#pragma unroll
    for (int k = 1; k < 8; k++) {
        float nm = fmaxf(M, sm[k]);
        S = S * __expf(M - nm) + ss[k] * __expf(sm[k] - nm);
        M = nm;
    }
    float lse = M + logf(S);

    for (int i = tid; i < n4; i += 256) {
        float4 v = r4[i];
        v.x -= lse; v.y -= lse; v.z -= lse; v.w -= lse;
        r4[i] = v;
    }
}

// ---------------- launcher ----------------
extern "C" void kernel_launch(void* const* d_in, const int* in_sizes, int n_in,
                              void* d_out, int out_size)
{
    const float* vid  = (const float*)d_in[0];
    const int*   tgt  = (const int*)  d_in[1];
    const float* emb  = (const float*)d_in[2];
    const float* Wih1 = (const float*)d_in[3];
    const float* Whh1 = (const float*)d_in[4];
    const float* bih1 = (const float*)d_in[5];
    const float* bhh1 = (const float*)d_in[6];
    const float* Wih2 = (const float*)d_in[7];
    const float* Whh2 = (const float*)d_in[8];
    const float* bih2 = (const float*)d_in[9];
    const float* bhh2 = (const float*)d_in[10];
    const float* Wout = (const float*)d_in[11];
    const float* bout = (const float*)d_in[12];
    float* out = (float*)d_out;

    cudaFuncSetAttribute(gemm_kernel<256>, cudaFuncAttributeMaxDynamicSharedMemorySize, SM_G256);
    cudaFuncSetAttribute(recurrence_kernel, cudaFuncAttributeMaxDynamicSharedMemorySize, SM_REC);

    bf16 *pWih1, *pWhh1, *pWih2, *pWhh2, *pWout, *pVid, *pWords, *ph1b, *ph2b, *pH2all;
    float *pGI1, *pGI2w, *ph1, *ph2;
    cudaGetSymbolAddress((void**)&pWih1, g_Wih1);
    cudaGetSymbolAddress((void**)&pWhh1, g_Whh1);
    cudaGetSymbolAddress((void**)&pWih2, g_Wih2);
    cudaGetSymbolAddress((void**)&pWhh2, g_Whh2);
    cudaGetSymbolAddress((void**)&pWout, g_Wout);
    cudaGetSymbolAddress((void**)&pVid,  g_vid);
    cudaGetSymbolAddress((void**)&pWords,g_words);
    cudaGetSymbolAddress((void**)&pGI1,  g_GI1);
    cudaGetSymbolAddress((void**)&pGI2w, g_GI2w);
    cudaGetSymbolAddress((void**)&ph1,   g_h1);
    cudaGetSymbolAddress((void**)&ph2,   g_h2);
    cudaGetSymbolAddress((void**)&ph1b,  g_h1b);
    cudaGetSymbolAddress((void**)&ph2b,  g_h2b);
    cudaGetSymbolAddress((void**)&pH2all,g_H2all);

    // 0: fused prep (weight conversions + vid permute + word gather)
    prep_kernel<<<2048, 256>>>(Wih1, pWih1, Whh1, pWhh1, Wih2, pWih2,
                               Whh2, pWhh2, Wout, pWout,
                               vid, pVid, tgt, emb, pWords);

    // 1: GI1 = vid @ W_ih1^T + b_ih1   (2560 x 3072 x 2048)
    gemm_kernel<256><<<dim3(G3/256, (T_VID*BATCH)/64), 256, SM_G256>>>(
        pVid, D_VID, pWih1, D_VID, pGI1, G3, bih1, D_VID, 0);
    // 2: GI2w = words @ W_ih2[:,H:]^T  (1728 x 3072 x 512), no bias
    gemm_kernel<256><<<dim3(G3/256, MROWS/64), 256, SM_G256>>>(
        pWords, WDIM, pWih2 + HDIM, HDIM+WDIM, pGI2w, G3, nullptr, WDIM, 0);

    // 3: persistent recurrence (all 67 steps, quartered bulk loader)
    recurrence_kernel<<<RBLK, 256, SM_REC>>>(
        pWhh1, pWih2, pWhh2,
        bih1, bhh1, bih2, bhh2,
        pGI1, pGI2w,
        ph1, ph2, ph1b, ph2b, pH2all);

    // 4: logits (1728 x 32000 x 1024), permuted into d_out, 2 CTAs/SM
    gemm_kernel<256><<<dim3(VOCAB/256, MROWS/64), 256, SM_G256>>>(
        pH2all, HDIM, pWout, HDIM, out, VOCAB, bout, HDIM, 1);

    // 5: online log_softmax
    logsoftmax_kernel<<<DECSTEPS*BATCH, 256>>>(out);
}

// round 15
// speedup vs baseline: 1.0016x; 1.0016x over previous
#include <cuda_runtime.h>
#include <cuda_bf16.h>

typedef __nv_bfloat16 bf16;

// ---------------- problem constants ----------------
#define BATCH   64
#define T_VID   40
#define D_VID   2048
#define HDIM    1024
#define WDIM    512
#define VOCAB   32000
#define MAXLEN  28
#define DECSTEPS (MAXLEN-1)          // 27
#define NSTEPS  (T_VID + DECSTEPS)   // 67
#define G3      (3*HDIM)             // 3072
#define MROWS   (DECSTEPS*BATCH)     // 1728

// ---------------- big-GEMM tiling (proven R7: 64 x 256, BK=64, 2-stage) ----------------
#define SKEW 8
#define SSTRIDE (64+SKEW)            // 72
#define ASZ (64*SSTRIDE)             // 4608
#define SM_G256 ((2*ASZ + 2*256*SSTRIDE)*2)  // 92160

// ---------------- recurrence tiling: full-K resident block, quartered bulk loader ----------------
#define RBLK 64                      // recurrence CTAs (16 h-cols each)
#define RSTRIDE 1032                 // 1024 + 8 skew elems; row pitch 2064 B (16B-aligned)
#define RA_ROWS 64
#define RB_ROWS 48
#define SM_REC ((RA_ROWS+RB_ROWS)*RSTRIDE*2)   // 231168 bytes
#define QBYTES ((RA_ROWS+RB_ROWS)*512u)        // 57344 bytes per K-quarter

// ---------------- device scratch ----------------
__device__ bf16  g_Wih1[(size_t)G3*D_VID];
__device__ bf16  g_Whh1[(size_t)G3*HDIM];
__device__ bf16  g_Wih2[(size_t)G3*(HDIM+WDIM)];
__device__ bf16  g_Whh2[(size_t)G3*HDIM];
__device__ bf16  g_Wout[(size_t)VOCAB*HDIM];
__device__ bf16  g_vid [(size_t)T_VID*BATCH*D_VID];
__device__ bf16  g_words[(size_t)MROWS*WDIM];
__device__ float g_GI1 [(size_t)T_VID*BATCH*G3];
__device__ float g_GI2w[(size_t)MROWS*G3];
__device__ float g_h1  [(size_t)BATCH*HDIM];
__device__ float g_h2  [(size_t)BATCH*HDIM];
__device__ bf16  g_h1b [2*(size_t)BATCH*HDIM];   // double-buffered bf16 copies
__device__ bf16  g_h2b [2*(size_t)BATCH*HDIM];
__device__ bf16  g_H2all[(size_t)MROWS*HDIM];

// barrier state (sense-reversing, survives graph replays)
__device__ unsigned g_bar_count = 0;
__device__ volatile unsigned g_bar_sense = 0;

// ---------------- helpers ----------------
__device__ __forceinline__ void cp16(void* s, const void* g) {
    unsigned sa = (unsigned)__cvta_generic_to_shared(s);
    asm volatile("cp.async.cg.shared.global [%0], [%1], 16;\n" :: "r"(sa), "l"(g));
}
__device__ __forceinline__ void cp_commit() {
    asm volatile("cp.async.commit_group;\n" ::: "memory");
}
__device__ __forceinline__ void cp_wait0() {
    asm volatile("cp.async.wait_group 0;\n" ::: "memory");
}
__device__ __forceinline__ void mma16816(float* c, const unsigned* a, const unsigned* b) {
    asm volatile(
        "mma.sync.aligned.m16n8k16.row.col.f32.bf16.bf16.f32 "
        "{%0,%1,%2,%3}, {%4,%5,%6,%7}, {%8,%9}, {%0,%1,%2,%3};\n"
        : "+f"(c[0]), "+f"(c[1]), "+f"(c[2]), "+f"(c[3])
        : "r"(a[0]), "r"(a[1]), "r"(a[2]), "r"(a[3]), "r"(b[0]), "r"(b[1]));
}
__device__ __forceinline__ float sigmf(float x) { return 1.f / (1.f + expf(-x)); }

// bulk async copy global->shared with mbarrier transaction completion
__device__ __forceinline__ void bulk_cp(unsigned dst_smem, const void* src, unsigned bytes,
                                        unsigned mbar) {
    asm volatile(
        "cp.async.bulk.shared::cluster.global.mbarrier::complete_tx::bytes [%0], [%1], %2, [%3];"
        :: "r"(dst_smem), "l"(src), "r"(bytes), "r"(mbar) : "memory");
}
__device__ __forceinline__ void mbar_init(unsigned mbar, unsigned count) {
    asm volatile("mbarrier.init.shared.b64 [%0], %1;" :: "r"(mbar), "r"(count) : "memory");
}
__device__ __forceinline__ void mbar_expect_tx(unsigned mbar, unsigned bytes) {
    asm volatile("mbarrier.arrive.expect_tx.shared.b64 _, [%0], %1;"
                 :: "r"(mbar), "r"(bytes) : "memory");
}
__device__ __forceinline__ void mbar_wait(unsigned mbar, unsigned parity) {
    asm volatile(
        "{\n\t"
        ".reg .pred P1;\n\t"
        "WAIT_LOOP_%=:\n\t"
        "mbarrier.try_wait.parity.acquire.cta.shared::cta.b64 P1, [%0], %1, 0x989680;\n\t"
        "@P1 bra.uni WAIT_DONE_%=;\n\t"
        "bra.uni WAIT_LOOP_%=;\n\t"
        "WAIT_DONE_%=:\n\t"
        "}"
        :: "r"(mbar), "r"(parity) : "memory");
}

// ==================== proven big GEMM (R7 + 2 CTAs/SM): C = A @ B^T (+bias) ====================
template<int TBN>
__global__ void __launch_bounds__(256, 2)
gemm_kernel(const bf16* __restrict__ A, int lda,
            const bf16* __restrict__ B, int ldb,
            float* __restrict__ C, int ldc,
            const float* __restrict__ bias,
            int K, int permute_out)
{
    constexpr int NI   = TBN / 32;
    constexpr int BSZT = TBN * SSTRIDE;

    extern __shared__ bf16 smem[];
    bf16* sA = smem;
    bf16* sB = smem + 2*ASZ;

    const int tid  = threadIdx.x;
    const int lane = tid & 31;
    const int warp = tid >> 5;
    const int wm   = warp & 1;
    const int wn   = warp >> 1;
    const int bm   = blockIdx.y * 64;
    const int bn   = blockIdx.x * TBN;

    float acc[2][NI][4];
#pragma unroll
    for (int mi = 0; mi < 2; mi++)
#pragma unroll
        for (int ni = 0; ni < NI; ni++)
#pragma unroll
            for (int q = 0; q < 4; q++) acc[mi][ni][q] = 0.f;

    const int KT = K >> 6;

    auto issue_stage = [&](int st, int kt) {
        const int k0 = kt << 6;
#pragma unroll
        for (int i = 0; i < 2; i++) {
            int ch = tid + (i << 8);
            int r = ch >> 3, c = (ch & 7) << 3;
            cp16(&sA[st*ASZ + r*SSTRIDE + c], A + (size_t)(bm + r)*lda + k0 + c);
        }
#pragma unroll
        for (int i = 0; i < NI; i++) {
            int ch = tid + (i << 8);
            int r = ch >> 3, c = (ch & 7) << 3;
            cp16(&sB[st*BSZT + r*SSTRIDE + c], B + (size_t)(bn + r)*ldb + k0 + c);
        }
        cp_commit();
    };

    issue_stage(0, 0);

    for (int kt = 0; kt < KT; kt++) {
        cp_wait0();
        __syncthreads();
        if (kt + 1 < KT) issue_stage((kt + 1) & 1, kt + 1);

        const bf16* a = sA + (kt & 1) * ASZ;
        const bf16* b = sB + (kt & 1) * BSZT;

#pragma unroll
        for (int kk = 0; kk < 4; kk++) {
            const int kc = kk * 16 + ((lane & 3) << 1);
            unsigned af[2][4];
#pragma unroll
            for (int mi = 0; mi < 2; mi++) {
                int r = wm * 32 + mi * 16 + (lane >> 2);
                af[mi][0] = *(const unsigned*)(a + (size_t)r * SSTRIDE + kc);
                af[mi][1] = *(const unsigned*)(a + (size_t)(r + 8) * SSTRIDE + kc);
                af[mi][2] = *(const unsigned*)(a + (size_t)r * SSTRIDE + kc + 8);
                af[mi][3] = *(const unsigned*)(a + (size_t)(r + 8) * SSTRIDE + kc + 8);
            }
            unsigned bfr[NI][2];
#pragma unroll
            for (int ni = 0; ni < NI; ni++) {
                int r = wn * (TBN/4) + ni * 8 + (lane >> 2);
                bfr[ni][0] = *(const unsigned*)(b + (size_t)r * SSTRIDE + kc);
                bfr[ni][1] = *(const unsigned*)(b + (size_t)r * SSTRIDE + kc + 8);
            }
#pragma unroll
            for (int mi = 0; mi < 2; mi++)
#pragma unroll
                for (int ni = 0; ni < NI; ni++)
                    mma16816(acc[mi][ni], af[mi], bfr[ni]);
        }
        __syncthreads();
    }

#pragma unroll
    for (int mi = 0; mi < 2; mi++) {
#pragma unroll
        for (int ni = 0; ni < NI; ni++) {
            int r0 = wm * 32 + mi * 16 + (lane >> 2);
            int c0 = bn + wn * (TBN/4) + ni * 8 + ((lane & 3) << 1);
#pragma unroll
            for (int p = 0; p < 2; p++) {
                int row = bm + r0 + p * 8;
                float x0 = acc[mi][ni][p * 2 + 0];
                float x1 = acc[mi][ni][p * 2 + 1];
                if (bias) { x0 += __ldg(bias + c0); x1 += __ldg(bias + c0 + 1); }
                size_t orow = permute_out ? (size_t)((row & 63) * DECSTEPS + (row >> 6))
                                          : (size_t)row;
                *(float2*)(C + orow * (size_t)ldc + c0) = make_float2(x0, x1);
            }
        }
    }
}

// ==================== persistent recurrence megakernel (quartered bulk loader) ====================
// 64 CTAs x 256 threads. CTA c owns h columns [16c, 16c+16).
// Per step: block gh1 | gate1 | block gh2 | gsync | block gi2 | gate2 | gsync.
// Each block loads A(64x1024) + B(48x1024) as 4 K-quarter transactions (4 mbarriers,
// 112 x 512B bulk copies per quarter), then wait-q/compute-q overlapped:
// quarter q's MMA runs while quarters q+1..3 are still in flight.
// Single smem allocation per block; expect_tx -> __syncthreads -> issue -> monotone waits.
__global__ void __launch_bounds__(256, 1)
recurrence_kernel(const bf16* __restrict__ Whh1,
                  const bf16* __restrict__ Wih2,
                  const bf16* __restrict__ Whh2,
                  const float* __restrict__ bih1,
                  const float* __restrict__ bhh1,
                  const float* __restrict__ bih2,
                  const float* __restrict__ bhh2,
                  const float* __restrict__ GI1,
                  const float* __restrict__ GI2w,
                  float* h1, float* h2, bf16* h1bb, bf16* h2bb, bf16* H2all)
{
    extern __shared__ bf16 smem[];
    __shared__ __align__(8) unsigned long long s_mbar[4];
    const int cid  = blockIdx.x;
    const int tid  = threadIdx.x;
    const int lane = tid & 31;
    const int warp = tid >> 5;
    const int wm   = warp & 3;       // 4 row-groups of 16
    const int wn   = warp >> 2;      // 2 col-halves of 8

    const unsigned smem_b = (unsigned)__cvta_generic_to_shared(smem);
    const unsigned mbar0  = (unsigned)__cvta_generic_to_shared(&s_mbar[0]);
    int bphase = 0;                  // phase parity for all 4 barriers (flips per block)

    __shared__ unsigned s_sense;
    if (tid == 0) {
        s_sense = g_bar_sense;
#pragma unroll
        for (int q = 0; q < 4; q++) mbar_init(mbar0 + q * 8, 1);
    }
    __syncthreads();

    auto gsync = [&]() {
        __syncthreads();
        if (tid == 0) {
            unsigned ls = s_sense ^ 1u;
            s_sense = ls;
            __threadfence();
            if (atomicAdd(&g_bar_count, 1u) == RBLK - 1) {
                atomicExch(&g_bar_count, 0u);
                __threadfence();
                g_bar_sense = ls;
            } else {
                while (g_bar_sense != ls) __nanosleep(32);
            }
        }
        __syncthreads();
    };

    // MMA over one quarter (16 k-chunks of 16): 3 gate accumulators.
    auto mmq = [&](int q, float* aR, float* aZ, float* aN) {
        const bf16* a = smem;
        const bf16* b = smem + (size_t)RA_ROWS * RSTRIDE;
#pragma unroll
        for (int kk2 = 0; kk2 < 16; kk2++) {
            const int kk = (q << 4) + kk2;
            const int kc = (kk << 4) + ((lane & 3) << 1);
            unsigned af[4];
            int r = (wm << 4) + (lane >> 2);
            af[0] = *(const unsigned*)(a + (size_t)r * RSTRIDE + kc);
            af[1] = *(const unsigned*)(a + (size_t)(r + 8) * RSTRIDE + kc);
            af[2] = *(const unsigned*)(a + (size_t)r * RSTRIDE + kc + 8);
            af[3] = *(const unsigned*)(a + (size_t)(r + 8) * RSTRIDE + kc + 8);
            int b0r = (wn << 3) + (lane >> 2);
            {
                unsigned bb[2] = { *(const unsigned*)(b + (size_t)b0r * RSTRIDE + kc),
                                   *(const unsigned*)(b + (size_t)b0r * RSTRIDE + kc + 8) };
                mma16816(aR, af, bb);
            }
            {
                int br = 16 + b0r;
                unsigned bb[2] = { *(const unsigned*)(b + (size_t)br * RSTRIDE + kc),
                                   *(const unsigned*)(b + (size_t)br * RSTRIDE + kc + 8) };
                mma16816(aZ, af, bb);
            }
            {
                int br = 32 + b0r;
                unsigned bb[2] = { *(const unsigned*)(b + (size_t)br * RSTRIDE + kc),
                                   *(const unsigned*)(b + (size_t)br * RSTRIDE + kc + 8) };
                mma16816(aN, af, bb);
            }
        }
    };

    // full block: 4 quartered bulk transactions; overlap wait-q with compute of q-1.
    auto block_gemm = [&](const bf16* Asrc, const bf16* Bsrc, int ldb,
                          float* aR, float* aZ, float* aN) {
        if (tid == 0) {
#pragma unroll
            for (int q = 0; q < 4; q++) mbar_expect_tx(mbar0 + q * 8, QBYTES);
        }
        __syncthreads();   // expect_tx set AND all threads done reading previous block
        if (tid < RA_ROWS) {
            const bf16* src = Asrc + (size_t)tid * HDIM;
            unsigned dst = smem_b + tid * (RSTRIDE * 2);
#pragma unroll
            for (int q = 0; q < 4; q++)
                bulk_cp(dst + q * 512, src + q * 256, 512, mbar0 + q * 8);
        } else if (tid < RA_ROWS + RB_ROWS) {
            int br = tid - RA_ROWS;
            int grow = (br >> 4) * HDIM + (cid << 4) + (br & 15);
            const bf16* src = Bsrc + (size_t)grow * ldb;
            unsigned dst = smem_b + (RA_ROWS + br) * (RSTRIDE * 2);
#pragma unroll
            for (int q = 0; q < 4; q++)
                bulk_cp(dst + q * 512, src + q * 256, 512, mbar0 + q * 8);
        }
#pragma unroll
        for (int q = 0; q < 4; q++) {
            mbar_wait(mbar0 + q * 8, (unsigned)bphase);
            mmq(q, aR, aZ, aN);
        }
        bphase ^= 1;
    };

    // ---- zero initial state (fp32 + bf16 buffer 0) ----
    for (int i = cid * 256 + tid; i < BATCH * HDIM; i += RBLK * 256) {
        __stcg(h1 + i, 0.f);
        __stcg(h2 + i, 0.f);
        __stcg((unsigned short*)h1bb + i, (unsigned short)0);
        __stcg((unsigned short*)h2bb + i, (unsigned short)0);
    }
    gsync();

    for (int t = 0; t < NSTEPS; t++) {
        const bool enc = (t < T_VID);
        const int p = t & 1;
        const bf16* h1r = h1bb + (size_t)p       * BATCH * HDIM;   // read buffer
        bf16*       h1w = h1bb + (size_t)(p ^ 1) * BATCH * HDIM;   // write buffer
        const bf16* h2r = h2bb + (size_t)p       * BATCH * HDIM;
        bf16*       h2w = h2bb + (size_t)(p ^ 1) * BATCH * HDIM;

        // ---- block 1: gh1 = h1r @ Whh1^T ----
        float aR1[4] = {0,0,0,0}, aZ1[4] = {0,0,0,0}, aN1[4] = {0,0,0,0};
        block_gemm(h1r, Whh1, HDIM, aR1, aZ1, aN1);

        // ---- gate1 epilogue -> h1 (fp32), h1w (bf16) ----
        {
            const float* git = enc ? (GI1 + (size_t)t * BATCH * G3) : bih1;
            const int gstride = enc ? G3 : 0;
#pragma unroll
            for (int pp = 0; pp < 2; pp++) {
#pragma unroll
                for (int q = 0; q < 2; q++) {
                    int row = (wm << 4) + (lane >> 2) + (pp << 3);
                    int j = (cid << 4) + (wn << 3) + ((lane & 3) << 1) + q;
                    int idx = (pp << 1) + q;
                    const float* gp = git + (size_t)row * gstride;
                    float rr = sigmf(gp[j]          + aR1[idx] + __ldg(bhh1 + j));
                    float zz = sigmf(gp[j + HDIM]   + aZ1[idx] + __ldg(bhh1 + j + HDIM));
                    float nn = tanhf(gp[j + 2*HDIM] + rr * (aN1[idx] + __ldg(bhh1 + j + 2*HDIM)));
                    int o = row * HDIM + j;
                    float hv = (1.f - zz) * nn + zz * __ldcg(h1 + o);
                    __stcg(h1 + o, hv);
                    __stcg((unsigned short*)h1w + o,
                           __bfloat16_as_ushort(__float2bfloat16(hv)));
                }
            }
        }

        // ---- block 2: gh2 = h2r @ Whh2^T (independent of gate1; pre-barrier) ----
        float aR2[4] = {0,0,0,0}, aZ2[4] = {0,0,0,0}, aNh[4] = {0,0,0,0};
        block_gemm(h2r, Whh2, HDIM, aR2, aZ2, aNh);
        gsync();   // all h1w writes complete chip-wide

        // ---- block 3: gi2 = h1w @ Wih2[:, :H]^T ----
        float aRi[4] = {0,0,0,0}, aZi[4] = {0,0,0,0}, aNi[4] = {0,0,0,0};
        block_gemm(h1w, Wih2, HDIM + WDIM, aRi, aZi, aNi);

        // ---- gate2 epilogue (combines block 2 + block 3 accumulators) ----
        {
            const int td = t - T_VID;
            bf16* h2save = enc ? nullptr : (H2all + (size_t)td * BATCH * HDIM);
#pragma unroll
            for (int pp = 0; pp < 2; pp++) {
#pragma unroll
                for (int q = 0; q < 2; q++) {
                    int row = (wm << 4) + (lane >> 2) + (pp << 3);
                    int j = (cid << 4) + (wn << 3) + ((lane & 3) << 1) + q;
                    int idx = (pp << 1) + q;
                    float wr = 0.f, wz = 0.f, wn_ = 0.f;
                    if (!enc) {
                        const float* w = GI2w + ((size_t)td * BATCH + row) * G3;
                        wr  = __ldcg(w + j);
                        wz  = __ldcg(w + j + HDIM);
                        wn_ = __ldcg(w + j + 2*HDIM);
                    }
                    float rr = sigmf(aRi[idx] + aR2[idx] + __ldg(bih2 + j) + __ldg(bhh2 + j) + wr);
                    float zz = sigmf(aZi[idx] + aZ2[idx] + __ldg(bih2 + j + HDIM) + __ldg(bhh2 + j + HDIM) + wz);
                    float nn = tanhf(aNi[idx] + __ldg(bih2 + j + 2*HDIM) + wn_
                                     + rr * (aNh[idx] + __ldg(bhh2 + j + 2*HDIM)));
                    int o = row * HDIM + j;
                    float hv = (1.f - zz) * nn + zz * __ldcg(h2 + o);
                    __stcg(h2 + o, hv);
                    unsigned short us = __bfloat16_as_ushort(__float2bfloat16(hv));
                    __stcg((unsigned short*)h2w + o, us);
                    if (h2save) __stcg((unsigned short*)h2save + o, us);
                }
            }
        }
        gsync();
    }
}

// ---------------- fused prep: 5 weight conversions + vid permute + word gather ----------------
#define CN1 ((long)G3*D_VID/2)
#define CN2 ((long)G3*HDIM/2)
#define CN3 ((long)G3*(HDIM+WDIM)/2)
#define CN4 ((long)G3*HDIM/2)
#define CN5 ((long)VOCAB*HDIM/2)
#define CNW (CN1+CN2+CN3+CN4+CN5)
#define PN_VID ((long)T_VID*BATCH*(D_VID/2))
#define PN_WRD ((long)MROWS*(WDIM/2))
__global__ void prep_kernel(const float* __restrict__ a1, bf16* o1,
                            const float* __restrict__ a2, bf16* o2,
                            const float* __restrict__ a3, bf16* o3,
                            const float* __restrict__ a4, bf16* o4,
                            const float* __restrict__ a5, bf16* o5,
                            const float* __restrict__ vid, bf16* __restrict__ vout,
                            const int* __restrict__ tgt, const float* __restrict__ emb,
                            bf16* __restrict__ wout)
{
    const long total = CNW + PN_VID + PN_WRD;
    long i = blockIdx.x * 256L + threadIdx.x;
    long stride = (long)gridDim.x * 256;
    for (; i < total; i += stride) {
        if (i < CNW) {
            const float2* src; __nv_bfloat162* dst; long j = i;
            if (j < CN1) { src = (const float2*)a1; dst = (__nv_bfloat162*)o1; }
            else if ((j -= CN1) < CN2) { src = (const float2*)a2; dst = (__nv_bfloat162*)o2; }
            else if ((j -= CN2) < CN3) { src = (const float2*)a3; dst = (__nv_bfloat162*)o3; }
            else if ((j -= CN3) < CN4) { src = (const float2*)a4; dst = (__nv_bfloat162*)o4; }
            else { j -= CN4; src = (const float2*)a5; dst = (__nv_bfloat162*)o5; }
            dst[j] = __float22bfloat162_rn(src[j]);
        } else if (i < CNW + PN_VID) {
            long k = i - CNW;
            long d2 = k & (D_VID/2 - 1);
            long tb = k >> 10;
            long b = tb & 63, t = tb >> 6;
            float2 v = ((const float2*)vid)[((b * T_VID + t) << 10) + d2];
            ((__nv_bfloat162*)vout)[k] = __float22bfloat162_rn(v);
        } else {
            long k = i - CNW - PN_VID;
            long j2 = k & (WDIM/2 - 1);
            long tb = k >> 8;
            long b = tb & 63, t = tb >> 6;
            int tok = tgt[b * MAXLEN + t];
            float2 v = ((const float2*)emb)[(long)tok * (WDIM/2) + j2];
            ((__nv_bfloat162*)wout)[k] = __float22bfloat162_rn(v);
        }
    }
}

// ---------------- online 2-pass log_softmax (rows of 32000 fp32) ----------------
__global__ void logsoftmax_kernel(float* __restrict__ data) {
    const int n4 = VOCAB / 4;
    float* row = data + (size_t)blockIdx.x * VOCAB;
    float4* r4 = (float4*)row;
    const int tid = threadIdx.x;
    const int lane = tid & 31, warp = tid >> 5;
    __shared__ float sm[8], ss[8];

    float m = -3.4e38f, s = 0.f;
    for (int i = tid; i < n4; i += 256) {
        float4 v = r4[i];
        float vv[4] = {v.x, v.y, v.z, v.w};
#pragma unroll
        for (int k = 0; k < 4; k++) {
            float x = vv[k];
            if (x > m) { s = s * __expf(m - x) + 1.f; m = x; }
            else         s += __expf(x - m);
        }
    }
#pragma unroll
    for (int o = 16; o; o >>= 1) {
        float om = __shfl_xor_sync(~0u, m, o);
        float os = __shfl_xor_sync(~0u, s, o);
        float nm = fmaxf(m, om);
        s = s * __expf(m - nm) + os * __expf(om - nm);
        m = nm;
    }
    if (lane == 0) { sm[warp] = m; ss[warp] = s; }
    __syncthreads();
    float M = sm[0], S = ss[0];
#pragma unroll
    for (int k = 1; k < 8; k++) {
        float nm = fmaxf(M, sm[k]);
        S = S * __expf(M - nm) + ss[k] * __expf(sm[k] - nm);
        M = nm;
    }
    float lse = M + logf(S);

    for (int i = tid; i < n4; i += 256) {
        float4 v = r4[i];
        v.x -= lse; v.y -= lse; v.z -= lse; v.w -= lse;
        r4[i] = v;
    }
}

// ---------------- launcher ----------------
extern "C" void kernel_launch(void* const* d_in, const int* in_sizes, int n_in,
                              void* d_out, int out_size)
{
    const float* vid  = (const float*)d_in[0];
    const int*   tgt  = (const int*)  d_in[1];
    const float* emb  = (const float*)d_in[2];
    const float* Wih1 = (const float*)d_in[3];
    const float* Whh1 = (const float*)d_in[4];
    const float* bih1 = (const float*)d_in[5];
    const float* bhh1 = (const float*)d_in[6];
    const float* Wih2 = (const float*)d_in[7];
    const float* Whh2 = (const float*)d_in[8];
    const float* bih2 = (const float*)d_in[9];
    const float* bhh2 = (const float*)d_in[10];
    const float* Wout = (const float*)d_in[11];
    const float* bout = (const float*)d_in[12];
    float* out = (float*)d_out;

    cudaFuncSetAttribute(gemm_kernel<256>, cudaFuncAttributeMaxDynamicSharedMemorySize, SM_G256);
    cudaFuncSetAttribute(recurrence_kernel, cudaFuncAttributeMaxDynamicSharedMemorySize, SM_REC);

    bf16 *pWih1, *pWhh1, *pWih2, *pWhh2, *pWout, *pVid, *pWords, *ph1b, *ph2b, *pH2all;
    float *pGI1, *pGI2w, *ph1, *ph2;
    cudaGetSymbolAddress((void**)&pWih1, g_Wih1);
    cudaGetSymbolAddress((void**)&pWhh1, g_Whh1);
    cudaGetSymbolAddress((void**)&pWih2, g_Wih2);
    cudaGetSymbolAddress((void**)&pWhh2, g_Whh2);
    cudaGetSymbolAddress((void**)&pWout, g_Wout);
    cudaGetSymbolAddress((void**)&pVid,  g_vid);
    cudaGetSymbolAddress((void**)&pWords,g_words);
    cudaGetSymbolAddress((void**)&pGI1,  g_GI1);
    cudaGetSymbolAddress((void**)&pGI2w, g_GI2w);
    cudaGetSymbolAddress((void**)&ph1,   g_h1);
    cudaGetSymbolAddress((void**)&ph2,   g_h2);
    cudaGetSymbolAddress((void**)&ph1b,  g_h1b);
    cudaGetSymbolAddress((void**)&ph2b,  g_h2b);
    cudaGetSymbolAddress((void**)&pH2all,g_H2all);

    // 0: fused prep (weight conversions + vid permute + word gather)
    prep_kernel<<<2048, 256>>>(Wih1, pWih1, Whh1, pWhh1, Wih2, pWih2,
                               Whh2, pWhh2, Wout, pWout,
                               vid, pVid, tgt, emb, pWords);

    // 1: GI1 = vid @ W_ih1^T + b_ih1   (2560 x 3072 x 2048)
    gemm_kernel<256><<<dim3(G3/256, (T_VID*BATCH)/64), 256, SM_G256>>>(
        pVid, D_VID, pWih1, D_VID, pGI1, G3, bih1, D_VID, 0);
    // 2: GI2w = words @ W_ih2[:,H:]^T  (1728 x 3072 x 512), no bias
    gemm_kernel<256><<<dim3(G3/256, MROWS/64), 256, SM_G256>>>(
        pWords, WDIM, pWih2 + HDIM, HDIM+WDIM, pGI2w, G3, nullptr, WDIM, 0);

    // 3: persistent recurrence (all 67 steps, quartered bulk loader)
    recurrence_kernel<<<RBLK, 256, SM_REC>>>(
        pWhh1, pWih2, pWhh2,
        bih1, bhh1, bih2, bhh2,
        pGI1, pGI2w,
        ph1, ph2, ph1b, ph2b, pH2all);

    // 4: logits (1728 x 32000 x 1024), permuted into d_out, 2 CTAs/SM
    gemm_kernel<256><<<dim3(VOCAB/256, MROWS/64), 256, SM_G256>>>(
        pH2all, HDIM, pWout, HDIM, out, VOCAB, bout, HDIM, 1);

    // 5: online log_softmax
    logsoftmax_kernel<<<DECSTEPS*BATCH, 256>>>(out);
}

// round 16
// speedup vs baseline: 1.0847x; 1.0830x over previous
#include <cuda_runtime.h>
#include <cuda_bf16.h>

typedef __nv_bfloat16 bf16;

// ---------------- problem constants ----------------
#define BATCH   64
#define T_VID   40
#define D_VID   2048
#define HDIM    1024
#define WDIM    512
#define VOCAB   32000
#define MAXLEN  28
#define DECSTEPS (MAXLEN-1)          // 27
#define NSTEPS  (T_VID + DECSTEPS)   // 67
#define G3      (3*HDIM)             // 3072
#define MROWS   (DECSTEPS*BATCH)     // 1728

// ---------------- big-GEMM tiling (proven R7: 64 x 256, BK=64, 2-stage) ----------------
#define SKEW 8
#define SSTRIDE (64+SKEW)            // 72
#define ASZ (64*SSTRIDE)             // 4608
#define SM_G256 ((2*ASZ + 2*256*SSTRIDE)*2)  // 92160

// ---------------- recurrence tiling: full-K resident block, bulk-copy loader (R13) ----------------
#define RBLK 64                      // recurrence CTAs (16 h-cols each)
#define RSTRIDE 1032                 // 1024 + 8 skew elems; row pitch 2064 B (16B-aligned)
#define RA_ROWS 64
#define RB_ROWS 48
#define SM_REC ((RA_ROWS+RB_ROWS)*RSTRIDE*2)   // 231168 bytes
#define BLK_BYTES ((RA_ROWS+RB_ROWS)*2048u)    // 229376 bytes per block load

// ---------------- device scratch ----------------
__device__ bf16  g_Wih1[(size_t)G3*D_VID];
__device__ bf16  g_Whh1[(size_t)G3*HDIM];
__device__ bf16  g_Wih2[(size_t)G3*(HDIM+WDIM)];
__device__ bf16  g_Whh2[(size_t)G3*HDIM];
__device__ bf16  g_Wout[(size_t)VOCAB*HDIM];
__device__ bf16  g_vid [(size_t)T_VID*BATCH*D_VID];
__device__ bf16  g_words[(size_t)MROWS*WDIM];
__device__ float g_GI1 [(size_t)T_VID*BATCH*G3];
__device__ float g_GI2w[(size_t)MROWS*G3];
__device__ float g_h1  [(size_t)BATCH*HDIM];
__device__ float g_h2  [(size_t)BATCH*HDIM];
__device__ bf16  g_h1b [2*(size_t)BATCH*HDIM];   // double-buffered bf16 copies
__device__ bf16  g_h2b [2*(size_t)BATCH*HDIM];
__device__ bf16  g_H2all[(size_t)MROWS*HDIM];

// barrier state (sense-reversing, survives graph replays)
__device__ unsigned g_bar_count = 0;
__device__ volatile unsigned g_bar_sense = 0;

// ---------------- helpers ----------------
__device__ __forceinline__ void cp16(void* s, const void* g) {
    unsigned sa = (unsigned)__cvta_generic_to_shared(s);
    asm volatile("cp.async.cg.shared.global [%0], [%1], 16;\n" :: "r"(sa), "l"(g));
}
__device__ __forceinline__ void cp_commit() {
    asm volatile("cp.async.commit_group;\n" ::: "memory");
}
__device__ __forceinline__ void cp_wait0() {
    asm volatile("cp.async.wait_group 0;\n" ::: "memory");
}
__device__ __forceinline__ void mma16816(float* c, const unsigned* a, const unsigned* b) {
    asm volatile(
        "mma.sync.aligned.m16n8k16.row.col.f32.bf16.bf16.f32 "
        "{%0,%1,%2,%3}, {%4,%5,%6,%7}, {%8,%9}, {%0,%1,%2,%3};\n"
        : "+f"(c[0]), "+f"(c[1]), "+f"(c[2]), "+f"(c[3])
        : "r"(a[0]), "r"(a[1]), "r"(a[2]), "r"(a[3]), "r"(b[0]), "r"(b[1]));
}
__device__ __forceinline__ float sigmf(float x) { return 1.f / (1.f + expf(-x)); }

// bulk async copy global->shared with mbarrier transaction completion
__device__ __forceinline__ void bulk_cp(unsigned dst_smem, const void* src, unsigned bytes,
                                        unsigned mbar) {
    asm volatile(
        "cp.async.bulk.shared::cluster.global.mbarrier::complete_tx::bytes [%0], [%1], %2, [%3];"
        :: "r"(dst_smem), "l"(src), "r"(bytes), "r"(mbar) : "memory");
}
__device__ __forceinline__ void mbar_init(unsigned mbar, unsigned count) {
    asm volatile("mbarrier.init.shared.b64 [%0], %1;" :: "r"(mbar), "r"(count) : "memory");
}
__device__ __forceinline__ void mbar_expect_tx(unsigned mbar, unsigned bytes) {
    asm volatile("mbarrier.arrive.expect_tx.shared.b64 _, [%0], %1;"
                 :: "r"(mbar), "r"(bytes) : "memory");
}
__device__ __forceinline__ void mbar_wait(unsigned mbar, unsigned parity) {
    asm volatile(
        "{\n\t"
        ".reg .pred P1;\n\t"
        "WAIT_LOOP_%=:\n\t"
        "mbarrier.try_wait.parity.acquire.cta.shared::cta.b64 P1, [%0], %1, 0x989680;\n\t"
        "@P1 bra.uni WAIT_DONE_%=;\n\t"
        "bra.uni WAIT_LOOP_%=;\n\t"
        "WAIT_DONE_%=:\n\t"
        "}"
        :: "r"(mbar), "r"(parity) : "memory");
}

// ==================== big GEMM (R7 tile + 2 CTAs/SM — this round's ONLY change) ====================
template<int TBN>
__global__ void __launch_bounds__(256, 2)
gemm_kernel(const bf16* __restrict__ A, int lda,
            const bf16* __restrict__ B, int ldb,
            float* __restrict__ C, int ldc,
            const float* __restrict__ bias,
            int K, int permute_out)
{
    constexpr int NI   = TBN / 32;
    constexpr int BSZT = TBN * SSTRIDE;

    extern __shared__ bf16 smem[];
    bf16* sA = smem;
    bf16* sB = smem + 2*ASZ;

    const int tid  = threadIdx.x;
    const int lane = tid & 31;
    const int warp = tid >> 5;
    const int wm   = warp & 1;
    const int wn   = warp >> 1;
    const int bm   = blockIdx.y * 64;
    const int bn   = blockIdx.x * TBN;

    float acc[2][NI][4];
#pragma unroll
    for (int mi = 0; mi < 2; mi++)
#pragma unroll
        for (int ni = 0; ni < NI; ni++)
#pragma unroll
            for (int q = 0; q < 4; q++) acc[mi][ni][q] = 0.f;

    const int KT = K >> 6;

    auto issue_stage = [&](int st, int kt) {
        const int k0 = kt << 6;
#pragma unroll
        for (int i = 0; i < 2; i++) {
            int ch = tid + (i << 8);
            int r = ch >> 3, c = (ch & 7) << 3;
            cp16(&sA[st*ASZ + r*SSTRIDE + c], A + (size_t)(bm + r)*lda + k0 + c);
        }
#pragma unroll
        for (int i = 0; i < NI; i++) {
            int ch = tid + (i << 8);
            int r = ch >> 3, c = (ch & 7) << 3;
            cp16(&sB[st*BSZT + r*SSTRIDE + c], B + (size_t)(bn + r)*ldb + k0 + c);
        }
        cp_commit();
    };

    issue_stage(0, 0);

    for (int kt = 0; kt < KT; kt++) {
        cp_wait0();
        __syncthreads();
        if (kt + 1 < KT) issue_stage((kt + 1) & 1, kt + 1);

        const bf16* a = sA + (kt & 1) * ASZ;
        const bf16* b = sB + (kt & 1) * BSZT;

#pragma unroll
        for (int kk = 0; kk < 4; kk++) {
            const int kc = kk * 16 + ((lane & 3) << 1);
            unsigned af[2][4];
#pragma unroll
            for (int mi = 0; mi < 2; mi++) {
                int r = wm * 32 + mi * 16 + (lane >> 2);
                af[mi][0] = *(const unsigned*)(a + (size_t)r * SSTRIDE + kc);
                af[mi][1] = *(const unsigned*)(a + (size_t)(r + 8) * SSTRIDE + kc);
                af[mi][2] = *(const unsigned*)(a + (size_t)r * SSTRIDE + kc + 8);
                af[mi][3] = *(const unsigned*)(a + (size_t)(r + 8) * SSTRIDE + kc + 8);
            }
            unsigned bfr[NI][2];
#pragma unroll
            for (int ni = 0; ni < NI; ni++) {
                int r = wn * (TBN/4) + ni * 8 + (lane >> 2);
                bfr[ni][0] = *(const unsigned*)(b + (size_t)r * SSTRIDE + kc);
                bfr[ni][1] = *(const unsigned*)(b + (size_t)r * SSTRIDE + kc + 8);
            }
#pragma unroll
            for (int mi = 0; mi < 2; mi++)
#pragma unroll
                for (int ni = 0; ni < NI; ni++)
                    mma16816(acc[mi][ni], af[mi], bfr[ni]);
        }
        __syncthreads();
    }

#pragma unroll
    for (int mi = 0; mi < 2; mi++) {
#pragma unroll
        for (int ni = 0; ni < NI; ni++) {
            int r0 = wm * 32 + mi * 16 + (lane >> 2);
            int c0 = bn + wn * (TBN/4) + ni * 8 + ((lane & 3) << 1);
#pragma unroll
            for (int p = 0; p < 2; p++) {
                int row = bm + r0 + p * 8;
                float x0 = acc[mi][ni][p * 2 + 0];
                float x1 = acc[mi][ni][p * 2 + 1];
                if (bias) { x0 += __ldg(bias + c0); x1 += __ldg(bias + c0 + 1); }
                size_t orow = permute_out ? (size_t)((row & 63) * DECSTEPS + (row >> 6))
                                          : (size_t)row;
                *(float2*)(C + orow * (size_t)ldc + c0) = make_float2(x0, x1);
            }
        }
    }
}

// ==================== persistent recurrence megakernel (R13 bulk-copy loader, proven) ====================
// 64 CTAs x 256 threads. CTA c owns h columns [16c, 16c+16).
// Per step: block gh1 | gate1 | block gh2 | gsync | block gi2 | gate2 | gsync.
// Each block: A(64x1024) + B(48x1024) loaded by 112 cp.async.bulk row copies (2KB each)
// with one mbarrier expect_tx. Ordering: expect_tx -> __syncthreads -> issue -> acquire-wait.
__global__ void __launch_bounds__(256, 1)
recurrence_kernel(const bf16* __restrict__ Whh1,
                  const bf16* __restrict__ Wih2,
                  const bf16* __restrict__ Whh2,
                  const float* __restrict__ bih1,
                  const float* __restrict__ bhh1,
                  const float* __restrict__ bih2,
                  const float* __restrict__ bhh2,
                  const float* __restrict__ GI1,
                  const float* __restrict__ GI2w,
                  float* h1, float* h2, bf16* h1bb, bf16* h2bb, bf16* H2all)
{
    extern __shared__ bf16 smem[];
    __shared__ __align__(8) unsigned long long s_mbar;
    const int cid  = blockIdx.x;
    const int tid  = threadIdx.x;
    const int lane = tid & 31;
    const int warp = tid >> 5;
    const int wm   = warp & 3;       // 4 row-groups of 16
    const int wn   = warp >> 2;      // 2 col-halves of 8

    const unsigned smem_b = (unsigned)__cvta_generic_to_shared(smem);
    const unsigned mbar   = (unsigned)__cvta_generic_to_shared(&s_mbar);
    int bphase = 0;                  // mbarrier phase parity (all threads in lockstep)

    __shared__ unsigned s_sense;
    if (tid == 0) {
        s_sense = g_bar_sense;
        mbar_init(mbar, 1);
    }
    __syncthreads();

    auto gsync = [&]() {
        __syncthreads();
        if (tid == 0) {
            unsigned ls = s_sense ^ 1u;
            s_sense = ls;
            __threadfence();
            if (atomicAdd(&g_bar_count, 1u) == RBLK - 1) {
                atomicExch(&g_bar_count, 0u);
                __threadfence();
                g_bar_sense = ls;
            } else {
                while (g_bar_sense != ls) __nanosleep(32);
            }
        }
        __syncthreads();
    };

    // MMA over one quarter (16 k-chunks of 16): 3 gate accumulators.
    auto mmq = [&](int q, float* aR, float* aZ, float* aN) {
        const bf16* a = smem;
        const bf16* b = smem + (size_t)RA_ROWS * RSTRIDE;
#pragma unroll
        for (int kk2 = 0; kk2 < 16; kk2++) {
            const int kk = (q << 4) + kk2;
            const int kc = (kk << 4) + ((lane & 3) << 1);
            unsigned af[4];
            int r = (wm << 4) + (lane >> 2);
            af[0] = *(const unsigned*)(a + (size_t)r * RSTRIDE + kc);
            af[1] = *(const unsigned*)(a + (size_t)(r + 8) * RSTRIDE + kc);
            af[2] = *(const unsigned*)(a + (size_t)r * RSTRIDE + kc + 8);
            af[3] = *(const unsigned*)(a + (size_t)(r + 8) * RSTRIDE + kc + 8);
            int b0r = (wn << 3) + (lane >> 2);
            {
                unsigned bb[2] = { *(const unsigned*)(b + (size_t)b0r * RSTRIDE + kc),
                                   *(const unsigned*)(b + (size_t)b0r * RSTRIDE + kc + 8) };
                mma16816(aR, af, bb);
            }
            {
                int br = 16 + b0r;
                unsigned bb[2] = { *(const unsigned*)(b + (size_t)br * RSTRIDE + kc),
                                   *(const unsigned*)(b + (size_t)br * RSTRIDE + kc + 8) };
                mma16816(aZ, af, bb);
            }
            {
                int br = 32 + b0r;
                unsigned bb[2] = { *(const unsigned*)(b + (size_t)br * RSTRIDE + kc),
                                   *(const unsigned*)(b + (size_t)br * RSTRIDE + kc + 8) };
                mma16816(aN, af, bb);
            }
        }
    };

    // full block: bulk-copy A (64 rows) + B (48 gate rows), wait, compute all 4 quarters.
    auto block_gemm = [&](const bf16* Asrc, const bf16* Bsrc, int ldb,
                          float* aR, float* aZ, float* aN) {
        if (tid == 0) mbar_expect_tx(mbar, BLK_BYTES);
        __syncthreads();   // expect_tx set AND all threads done reading previous block
        if (tid < RA_ROWS) {
            bulk_cp(smem_b + tid * (RSTRIDE * 2), Asrc + (size_t)tid * HDIM, 2048, mbar);
        } else if (tid < RA_ROWS + RB_ROWS) {
            int br = tid - RA_ROWS;
            int grow = (br >> 4) * HDIM + (cid << 4) + (br & 15);
            bulk_cp(smem_b + (RA_ROWS + br) * (RSTRIDE * 2),
                    Bsrc + (size_t)grow * ldb, 2048, mbar);
        }
        mbar_wait(mbar, (unsigned)bphase);
        bphase ^= 1;
        mmq(0, aR, aZ, aN);
        mmq(1, aR, aZ, aN);
        mmq(2, aR, aZ, aN);
        mmq(3, aR, aZ, aN);
    };

    // ---- zero initial state (fp32 + bf16 buffer 0) ----
    for (int i = cid * 256 + tid; i < BATCH * HDIM; i += RBLK * 256) {
        __stcg(h1 + i, 0.f);
        __stcg(h2 + i, 0.f);
        __stcg((unsigned short*)h1bb + i, (unsigned short)0);
        __stcg((unsigned short*)h2bb + i, (unsigned short)0);
    }
    gsync();

    for (int t = 0; t < NSTEPS; t++) {
        const bool enc = (t < T_VID);
        const int p = t & 1;
        const bf16* h1r = h1bb + (size_t)p       * BATCH * HDIM;   // read buffer
        bf16*       h1w = h1bb + (size_t)(p ^ 1) * BATCH * HDIM;   // write buffer
        const bf16* h2r = h2bb + (size_t)p       * BATCH * HDIM;
        bf16*       h2w = h2bb + (size_t)(p ^ 1) * BATCH * HDIM;

        // ---- block 1: gh1 = h1r @ Whh1^T ----
        float aR1[4] = {0,0,0,0}, aZ1[4] = {0,0,0,0}, aN1[4] = {0,0,0,0};
        block_gemm(h1r, Whh1, HDIM, aR1, aZ1, aN1);

        // ---- gate1 epilogue -> h1 (fp32), h1w (bf16) ----
        {
            const float* git = enc ? (GI1 + (size_t)t * BATCH * G3) : bih1;
            const int gstride = enc ? G3 : 0;
#pragma unroll
            for (int pp = 0; pp < 2; pp++) {
#pragma unroll
                for (int q = 0; q < 2; q++) {
                    int row = (wm << 4) + (lane >> 2) + (pp << 3);
                    int j = (cid << 4) + (wn << 3) + ((lane & 3) << 1) + q;
                    int idx = (pp << 1) + q;
                    const float* gp = git + (size_t)row * gstride;
                    float rr = sigmf(gp[j]          + aR1[idx] + __ldg(bhh1 + j));
                    float zz = sigmf(gp[j + HDIM]   + aZ1[idx] + __ldg(bhh1 + j + HDIM));
                    float nn = tanhf(gp[j + 2*HDIM] + rr * (aN1[idx] + __ldg(bhh1 + j + 2*HDIM)));
                    int o = row * HDIM + j;
                    float hv = (1.f - zz) * nn + zz * __ldcg(h1 + o);
                    __stcg(h1 + o, hv);
                    __stcg((unsigned short*)h1w + o,
                           __bfloat16_as_ushort(__float2bfloat16(hv)));
                }
            }
        }

        // ---- block 2: gh2 = h2r @ Whh2^T (independent of gate1; pre-barrier) ----
        float aR2[4] = {0,0,0,0}, aZ2[4] = {0,0,0,0}, aNh[4] = {0,0,0,0};
        block_gemm(h2r, Whh2, HDIM, aR2, aZ2, aNh);
        gsync();   // all h1w writes complete chip-wide

        // ---- block 3: gi2 = h1w @ Wih2[:, :H]^T ----
        float aRi[4] = {0,0,0,0}, aZi[4] = {0,0,0,0}, aNi[4] = {0,0,0,0};
        block_gemm(h1w, Wih2, HDIM + WDIM, aRi, aZi, aNi);

        // ---- gate2 epilogue (combines block 2 + block 3 accumulators) ----
        {
            const int td = t - T_VID;
            bf16* h2save = enc ? nullptr : (H2all + (size_t)td * BATCH * HDIM);
#pragma unroll
            for (int pp = 0; pp < 2; pp++) {
#pragma unroll
                for (int q = 0; q < 2; q++) {
                    int row = (wm << 4) + (lane >> 2) + (pp << 3);
                    int j = (cid << 4) + (wn << 3) + ((lane & 3) << 1) + q;
                    int idx = (pp << 1) + q;
                    float wr = 0.f, wz = 0.f, wn_ = 0.f;
                    if (!enc) {
                        const float* w = GI2w + ((size_t)td * BATCH + row) * G3;
                        wr  = __ldcg(w + j);
                        wz  = __ldcg(w + j + HDIM);
                        wn_ = __ldcg(w + j + 2*HDIM);
                    }
                    float rr = sigmf(aRi[idx] + aR2[idx] + __ldg(bih2 + j) + __ldg(bhh2 + j) + wr);
                    float zz = sigmf(aZi[idx] + aZ2[idx] + __ldg(bih2 + j + HDIM) + __ldg(bhh2 + j + HDIM) + wz);
                    float nn = tanhf(aNi[idx] + __ldg(bih2 + j + 2*HDIM) + wn_
                                     + rr * (aNh[idx] + __ldg(bhh2 + j + 2*HDIM)));
                    int o = row * HDIM + j;
                    float hv = (1.f - zz) * nn + zz * __ldcg(h2 + o);
                    __stcg(h2 + o, hv);
                    unsigned short us = __bfloat16_as_ushort(__float2bfloat16(hv));
                    __stcg((unsigned short*)h2w + o, us);
                    if (h2save) __stcg((unsigned short*)h2save + o, us);
                }
            }
        }
        gsync();
    }
}

// ---------------- fused prep: 5 weight conversions + vid permute + word gather ----------------
#define CN1 ((long)G3*D_VID/2)
#define CN2 ((long)G3*HDIM/2)
#define CN3 ((long)G3*(HDIM+WDIM)/2)
#define CN4 ((long)G3*HDIM/2)
#define CN5 ((long)VOCAB*HDIM/2)
#define CNW (CN1+CN2+CN3+CN4+CN5)
#define PN_VID ((long)T_VID*BATCH*(D_VID/2))
#define PN_WRD ((long)MROWS*(WDIM/2))
__global__ void prep_kernel(const float* __restrict__ a1, bf16* o1,
                            const float* __restrict__ a2, bf16* o2,
                            const float* __restrict__ a3, bf16* o3,
                            const float* __restrict__ a4, bf16* o4,
                            const float* __restrict__ a5, bf16* o5,
                            const float* __restrict__ vid, bf16* __restrict__ vout,
                            const int* __restrict__ tgt, const float* __restrict__ emb,
                            bf16* __restrict__ wout)
{
    const long total = CNW + PN_VID + PN_WRD;
    long i = blockIdx.x * 256L + threadIdx.x;
    long stride = (long)gridDim.x * 256;
    for (; i < total; i += stride) {
        if (i < CNW) {
            const float2* src; __nv_bfloat162* dst; long j = i;
            if (j < CN1) { src = (const float2*)a1; dst = (__nv_bfloat162*)o1; }
            else if ((j -= CN1) < CN2) { src = (const float2*)a2; dst = (__nv_bfloat162*)o2; }
            else if ((j -= CN2) < CN3) { src = (const float2*)a3; dst = (__nv_bfloat162*)o3; }
            else if ((j -= CN3) < CN4) { src = (const float2*)a4; dst = (__nv_bfloat162*)o4; }
            else { j -= CN4; src = (const float2*)a5; dst = (__nv_bfloat162*)o5; }
            dst[j] = __float22bfloat162_rn(src[j]);
        } else if (i < CNW + PN_VID) {
            long k = i - CNW;
            long d2 = k & (D_VID/2 - 1);
            long tb = k >> 10;
            long b = tb & 63, t = tb >> 6;
            float2 v = ((const float2*)vid)[((b * T_VID + t) << 10) + d2];
            ((__nv_bfloat162*)vout)[k] = __float22bfloat162_rn(v);
        } else {
            long k = i - CNW - PN_VID;
            long j2 = k & (WDIM/2 - 1);
            long tb = k >> 8;
            long b = tb & 63, t = tb >> 6;
            int tok = tgt[b * MAXLEN + t];
            float2 v = ((const float2*)emb)[(long)tok * (WDIM/2) + j2];
            ((__nv_bfloat162*)wout)[k] = __float22bfloat162_rn(v);
        }
    }
}

// ---------------- online 2-pass log_softmax (rows of 32000 fp32) ----------------
__global__ void logsoftmax_kernel(float* __restrict__ data) {
    const int n4 = VOCAB / 4;
    float* row = data + (size_t)blockIdx.x * VOCAB;
    float4* r4 = (float4*)row;
    const int tid = threadIdx.x;
    const int lane = tid & 31, warp = tid >> 5;
    __shared__ float sm[8], ss[8];

    float m = -3.4e38f, s = 0.f;
    for (int i = tid; i < n4; i += 256) {
        float4 v = r4[i];
        float vv[4] = {v.x, v.y, v.z, v.w};
#pragma unroll
        for (int k = 0; k < 4; k++) {
            float x = vv[k];
            if (x > m) { s = s * __expf(m - x) + 1.f; m = x; }
            else         s += __expf(x - m);
        }
    }
#pragma unroll
    for (int o = 16; o; o >>= 1) {
        float om = __shfl_xor_sync(~0u, m, o);
        float os = __shfl_xor_sync(~0u, s, o);
        float nm = fmaxf(m, om);
        s = s * __expf(m - nm) + os * __expf(om - nm);
        m = nm;
    }
    if (lane == 0) { sm[warp] = m; ss[warp] = s; }
    __syncthreads();
    float M = sm[0], S = ss[0];
#pragma unroll
    for (int k = 1; k < 8; k++) {
        float nm = fmaxf(M, sm[k]);
        S = S * __expf(M - nm) + ss[k] * __expf(sm[k] - nm);
        M = nm;
    }
    float lse = M + logf(S);

    for (int i = tid; i < n4; i += 256) {
        float4 v = r4[i];
        v.x -= lse; v.y -= lse; v.z -= lse; v.w -= lse;
        r4[i] = v;
    }
}

// ---------------- launcher ----------------
extern "C" void kernel_launch(void* const* d_in, const int* in_sizes, int n_in,
                              void* d_out, int out_size)
{
    const float* vid  = (const float*)d_in[0];
    const int*   tgt  = (const int*)  d_in[1];
    const float* emb  = (const float*)d_in[2];
    const float* Wih1 = (const float*)d_in[3];
    const float* Whh1 = (const float*)d_in[4];
    const float* bih1 = (const float*)d_in[5];
    const float* bhh1 = (const float*)d_in[6];
    const float* Wih2 = (const float*)d_in[7];
    const float* Whh2 = (const float*)d_in[8];
    const float* bih2 = (const float*)d_in[9];
    const float* bhh2 = (const float*)d_in[10];
    const float* Wout = (const float*)d_in[11];
    const float* bout = (const float*)d_in[12];
    float* out = (float*)d_out;

    cudaFuncSetAttribute(gemm_kernel<256>, cudaFuncAttributeMaxDynamicSharedMemorySize, SM_G256);
    cudaFuncSetAttribute(recurrence_kernel, cudaFuncAttributeMaxDynamicSharedMemorySize, SM_REC);

    bf16 *pWih1, *pWhh1, *pWih2, *pWhh2, *pWout, *pVid, *pWords, *ph1b, *ph2b, *pH2all;
    float *pGI1, *pGI2w, *ph1, *ph2;
    cudaGetSymbolAddress((void**)&pWih1, g_Wih1);
    cudaGetSymbolAddress((void**)&pWhh1, g_Whh1);
    cudaGetSymbolAddress((void**)&pWih2, g_Wih2);
    cudaGetSymbolAddress((void**)&pWhh2, g_Whh2);
    cudaGetSymbolAddress((void**)&pWout, g_Wout);
    cudaGetSymbolAddress((void**)&pVid,  g_vid);
    cudaGetSymbolAddress((void**)&pWords,g_words);
    cudaGetSymbolAddress((void**)&pGI1,  g_GI1);
    cudaGetSymbolAddress((void**)&pGI2w, g_GI2w);
    cudaGetSymbolAddress((void**)&ph1,   g_h1);
    cudaGetSymbolAddress((void**)&ph2,   g_h2);
    cudaGetSymbolAddress((void**)&ph1b,  g_h1b);
    cudaGetSymbolAddress((void**)&ph2b,  g_h2b);
    cudaGetSymbolAddress((void**)&pH2all,g_H2all);

    // 0: fused prep (weight conversions + vid permute + word gather)
    prep_kernel<<<2048, 256>>>(Wih1, pWih1, Whh1, pWhh1, Wih2, pWih2,
                               Whh2, pWhh2, Wout, pWout,
                               vid, pVid, tgt, emb, pWords);

    // 1: GI1 = vid @ W_ih1^T + b_ih1   (2560 x 3072 x 2048)
    gemm_kernel<256><<<dim3(G3/256, (T_VID*BATCH)/64), 256, SM_G256>>>(
        pVid, D_VID, pWih1, D_VID, pGI1, G3, bih1, D_VID, 0);
    // 2: GI2w = words @ W_ih2[:,H:]^T  (1728 x 3072 x 512), no bias
    gemm_kernel<256><<<dim3(G3/256, MROWS/64), 256, SM_G256>>>(
        pWords, WDIM, pWih2 + HDIM, HDIM+WDIM, pGI2w, G3, nullptr, WDIM, 0);

    // 3: persistent recurrence (all 67 steps, R13 bulk-copy loader)
    recurrence_kernel<<<RBLK, 256, SM_REC>>>(
        pWhh1, pWih2, pWhh2,
        bih1, bhh1, bih2, bhh2,
        pGI1, pGI2w,
        ph1, ph2, ph1b, ph2b, pH2all);

    // 4: logits (1728 x 32000 x 1024), permuted into d_out, 2 CTAs/SM
    gemm_kernel<256><<<dim3(VOCAB/256, MROWS/64), 256, SM_G256>>>(
        pH2all, HDIM, pWout, HDIM, out, VOCAB, bout, HDIM, 1);

    // 5: online log_softmax
    logsoftmax_kernel<<<DECSTEPS*BATCH, 256>>>(out);
}

// round 17
// speedup vs baseline: 1.1173x; 1.0300x over previous
#include <cuda_runtime.h>
#include <cuda_bf16.h>

typedef __nv_bfloat16 bf16;

// ---------------- problem constants ----------------
#define BATCH   64
#define T_VID   40
#define D_VID   2048
#define HDIM    1024
#define WDIM    512
#define VOCAB   32000
#define MAXLEN  28
#define DECSTEPS (MAXLEN-1)          // 27
#define NSTEPS  (T_VID + DECSTEPS)   // 67
#define G3      (3*HDIM)             // 3072
#define MROWS   (DECSTEPS*BATCH)     // 1728

// ---------------- big-GEMM tiling (64 x 256, BK=64, 2-stage) ----------------
#define SKEW 8
#define SSTRIDE (64+SKEW)            // 72 elems = 144 B rows (16B aligned, LDSM conflict-free)
#define ASZ (64*SSTRIDE)             // 4608
#define SM_G256 ((2*ASZ + 2*256*SSTRIDE)*2)  // 92160

// ---------------- recurrence tiling: full-K resident block, bulk-copy loader (R13) ----------------
#define RBLK 64                      // recurrence CTAs (16 h-cols each)
#define RSTRIDE 1032                 // 1024 + 8 skew elems; row pitch 2064 B (16B-aligned)
#define RA_ROWS 64
#define RB_ROWS 48
#define SM_REC ((RA_ROWS+RB_ROWS)*RSTRIDE*2)   // 231168 bytes
#define BLK_BYTES ((RA_ROWS+RB_ROWS)*2048u)    // 229376 bytes per block load

// ---------------- device scratch ----------------
__device__ bf16  g_Wih1[(size_t)G3*D_VID];
__device__ bf16  g_Whh1[(size_t)G3*HDIM];
__device__ bf16  g_Wih2[(size_t)G3*(HDIM+WDIM)];
__device__ bf16  g_Whh2[(size_t)G3*HDIM];
__device__ bf16  g_Wout[(size_t)VOCAB*HDIM];
__device__ bf16  g_vid [(size_t)T_VID*BATCH*D_VID];
__device__ bf16  g_words[(size_t)MROWS*WDIM];
__device__ float g_GI1 [(size_t)T_VID*BATCH*G3];
__device__ float g_GI2w[(size_t)MROWS*G3];
__device__ float g_h1  [(size_t)BATCH*HDIM];
__device__ float g_h2  [(size_t)BATCH*HDIM];
__device__ bf16  g_h1b [2*(size_t)BATCH*HDIM];   // double-buffered bf16 copies
__device__ bf16  g_h2b [2*(size_t)BATCH*HDIM];
__device__ bf16  g_H2all[(size_t)MROWS*HDIM];

// barrier state (sense-reversing, survives graph replays)
__device__ unsigned g_bar_count = 0;
__device__ volatile unsigned g_bar_sense = 0;

// ---------------- helpers ----------------
__device__ __forceinline__ void cp16(void* s, const void* g) {
    unsigned sa = (unsigned)__cvta_generic_to_shared(s);
    asm volatile("cp.async.cg.shared.global [%0], [%1], 16;\n" :: "r"(sa), "l"(g));
}
__device__ __forceinline__ void cp_commit() {
    asm volatile("cp.async.commit_group;\n" ::: "memory");
}
__device__ __forceinline__ void cp_wait0() {
    asm volatile("cp.async.wait_group 0;\n" ::: "memory");
}
__device__ __forceinline__ void mma16816(float* c, const unsigned* a, const unsigned* b) {
    asm volatile(
        "mma.sync.aligned.m16n8k16.row.col.f32.bf16.bf16.f32 "
        "{%0,%1,%2,%3}, {%4,%5,%6,%7}, {%8,%9}, {%0,%1,%2,%3};\n"
        : "+f"(c[0]), "+f"(c[1]), "+f"(c[2]), "+f"(c[3])
        : "r"(a[0]), "r"(a[1]), "r"(a[2]), "r"(a[3]), "r"(b[0]), "r"(b[1]));
}
__device__ __forceinline__ void ldsm_x4(unsigned& r0, unsigned& r1, unsigned& r2, unsigned& r3,
                                        unsigned addr) {
    asm volatile("ldmatrix.sync.aligned.m8n8.x4.shared.b16 {%0,%1,%2,%3}, [%4];"
        : "=r"(r0), "=r"(r1), "=r"(r2), "=r"(r3) : "r"(addr));
}
__device__ __forceinline__ void ldsm_x2(unsigned& r0, unsigned& r1, unsigned addr) {
    asm volatile("ldmatrix.sync.aligned.m8n8.x2.shared.b16 {%0,%1}, [%2];"
        : "=r"(r0), "=r"(r1) : "r"(addr));
}
__device__ __forceinline__ float sigmf(float x) { return 1.f / (1.f + expf(-x)); }

// bulk async copy global->shared with mbarrier transaction completion
__device__ __forceinline__ void bulk_cp(unsigned dst_smem, const void* src, unsigned bytes,
                                        unsigned mbar) {
    asm volatile(
        "cp.async.bulk.shared::cluster.global.mbarrier::complete_tx::bytes [%0], [%1], %2, [%3];"
        :: "r"(dst_smem), "l"(src), "r"(bytes), "r"(mbar) : "memory");
}
__device__ __forceinline__ void mbar_init(unsigned mbar, unsigned count) {
    asm volatile("mbarrier.init.shared.b64 [%0], %1;" :: "r"(mbar), "r"(count) : "memory");
}
__device__ __forceinline__ void mbar_expect_tx(unsigned mbar, unsigned bytes) {
    asm volatile("mbarrier.arrive.expect_tx.shared.b64 _, [%0], %1;"
                 :: "r"(mbar), "r"(bytes) : "memory");
}
__device__ __forceinline__ void mbar_wait(unsigned mbar, unsigned parity) {
    asm volatile(
        "{\n\t"
        ".reg .pred P1;\n\t"
        "WAIT_LOOP_%=:\n\t"
        "mbarrier.try_wait.parity.acquire.cta.shared::cta.b64 P1, [%0], %1, 0x989680;\n\t"
        "@P1 bra.uni WAIT_DONE_%=;\n\t"
        "bra.uni WAIT_LOOP_%=;\n\t"
        "WAIT_DONE_%=:\n\t"
        "}"
        :: "r"(mbar), "r"(parity) : "memory");
}

// ==================== big GEMM (64 x TBN, ldmatrix fragment loads) ====================
template<int TBN>
__global__ void __launch_bounds__(256)
gemm_kernel(const bf16* __restrict__ A, int lda,
            const bf16* __restrict__ B, int ldb,
            float* __restrict__ C, int ldc,
            const float* __restrict__ bias,
            int K, int permute_out)
{
    constexpr int NI   = TBN / 32;
    constexpr int NP   = NI / 2;             // ldmatrix.x4 pairs over N
    constexpr int BSZT = TBN * SSTRIDE;

    extern __shared__ bf16 smem[];
    bf16* sA = smem;
    bf16* sB = smem + 2*ASZ;

    const int tid  = threadIdx.x;
    const int lane = tid & 31;
    const int warp = tid >> 5;
    const int wm   = warp & 1;
    const int wn   = warp >> 1;
    const int bm   = blockIdx.y * 64;
    const int bn   = blockIdx.x * TBN;

    // ldmatrix per-thread address components
    const int lr = lane & 7;                 // row within 8x8 matrix
    const int g  = lane >> 3;                // matrix group 0..3
    const unsigned sA_b = (unsigned)__cvta_generic_to_shared(sA);
    const unsigned sB_b = (unsigned)__cvta_generic_to_shared(sB);
    // A tile mi: matrices (row, col): m0=(+lr,0) m1=(+8+lr,0) m2=(+lr,8) m3=(+8+lr,8)
    unsigned aoff[2];
#pragma unroll
    for (int mi = 0; mi < 2; mi++)
        aoff[mi] = (unsigned)(((wm*32 + mi*16 + lr + ((g & 1) << 3)) * SSTRIDE
                               + ((g >> 1) << 3)) * 2);
    // B pair p (ni=2p,2p+1): m0=(n2p+lr,0) m1=(n2p+lr,8) m2=(n2p+8+lr,0) m3=(n2p+8+lr,8)
    unsigned boff[NP];
#pragma unroll
    for (int p = 0; p < NP; p++)
        boff[p] = (unsigned)(((wn*(TBN/4) + (p << 4) + ((g >> 1) << 3) + lr) * SSTRIDE
                              + ((g & 1) << 3)) * 2);

    float acc[2][NI][4];
#pragma unroll
    for (int mi = 0; mi < 2; mi++)
#pragma unroll
        for (int ni = 0; ni < NI; ni++)
#pragma unroll
            for (int q = 0; q < 4; q++) acc[mi][ni][q] = 0.f;

    const int KT = K >> 6;

    auto issue_stage = [&](int st, int kt) {
        const int k0 = kt << 6;
#pragma unroll
        for (int i = 0; i < 2; i++) {
            int ch = tid + (i << 8);
            int r = ch >> 3, c = (ch & 7) << 3;
            cp16(&sA[st*ASZ + r*SSTRIDE + c], A + (size_t)(bm + r)*lda + k0 + c);
        }
#pragma unroll
        for (int i = 0; i < NI; i++) {
            int ch = tid + (i << 8);
            int r = ch >> 3, c = (ch & 7) << 3;
            cp16(&sB[st*BSZT + r*SSTRIDE + c], B + (size_t)(bn + r)*ldb + k0 + c);
        }
        cp_commit();
    };

    issue_stage(0, 0);

    for (int kt = 0; kt < KT; kt++) {
        cp_wait0();
        __syncthreads();
        if (kt + 1 < KT) issue_stage((kt + 1) & 1, kt + 1);

        const unsigned a_st = sA_b + (unsigned)((kt & 1) * ASZ * 2);
        const unsigned b_st = sB_b + (unsigned)((kt & 1) * BSZT * 2);

#pragma unroll
        for (int kk = 0; kk < 4; kk++) {
            const unsigned kb = kk * 32;     // 16 elems * 2B
            unsigned af[2][4];
#pragma unroll
            for (int mi = 0; mi < 2; mi++)
                ldsm_x4(af[mi][0], af[mi][1], af[mi][2], af[mi][3],
                        a_st + aoff[mi] + kb);
            unsigned bfr[NI][2];
#pragma unroll
            for (int p = 0; p < NP; p++) {
                unsigned r0, r1, r2, r3;
                ldsm_x4(r0, r1, r2, r3, b_st + boff[p] + kb);
                bfr[2*p][0] = r0;   bfr[2*p][1] = r1;
                bfr[2*p+1][0] = r2; bfr[2*p+1][1] = r3;
            }
#pragma unroll
            for (int mi = 0; mi < 2; mi++)
#pragma unroll
                for (int ni = 0; ni < NI; ni++)
                    mma16816(acc[mi][ni], af[mi], bfr[ni]);
        }
        __syncthreads();
    }

#pragma unroll
    for (int mi = 0; mi < 2; mi++) {
#pragma unroll
        for (int ni = 0; ni < NI; ni++) {
            int r0 = wm * 32 + mi * 16 + (lane >> 2);
            int c0 = bn + wn * (TBN/4) + ni * 8 + ((lane & 3) << 1);
#pragma unroll
            for (int p = 0; p < 2; p++) {
                int row = bm + r0 + p * 8;
                float x0 = acc[mi][ni][p * 2 + 0];
                float x1 = acc[mi][ni][p * 2 + 1];
                if (bias) { x0 += __ldg(bias + c0); x1 += __ldg(bias + c0 + 1); }
                size_t orow = permute_out ? (size_t)((row & 63) * DECSTEPS + (row >> 6))
                                          : (size_t)row;
                *(float2*)(C + orow * (size_t)ldc + c0) = make_float2(x0, x1);
            }
        }
    }
}

// ==================== persistent recurrence megakernel (R13 loader + ldmatrix mmq) ====================
// 64 CTAs x 256 threads. CTA c owns h columns [16c, 16c+16).
// Per step: block gh1 | gate1 | block gh2 | gsync | block gi2 | gate2 | gsync.
// Each block: A(64x1024) + B(48x1024) loaded by 112 cp.async.bulk row copies (2KB each)
// with one mbarrier expect_tx. Ordering: expect_tx -> __syncthreads -> issue -> acquire-wait.
__global__ void __launch_bounds__(256, 1)
recurrence_kernel(const bf16* __restrict__ Whh1,
                  const bf16* __restrict__ Wih2,
                  const bf16* __restrict__ Whh2,
                  const float* __restrict__ bih1,
                  const float* __restrict__ bhh1,
                  const float* __restrict__ bih2,
                  const float* __restrict__ bhh2,
                  const float* __restrict__ GI1,
                  const float* __restrict__ GI2w,
                  float* h1, float* h2, bf16* h1bb, bf16* h2bb, bf16* H2all)
{
    extern __shared__ bf16 smem[];
    __shared__ __align__(8) unsigned long long s_mbar;
    const int cid  = blockIdx.x;
    const int tid  = threadIdx.x;
    const int lane = tid & 31;
    const int warp = tid >> 5;
    const int wm   = warp & 3;       // 4 row-groups of 16
    const int wn   = warp >> 2;      // 2 col-halves of 8

    const unsigned smem_b = (unsigned)__cvta_generic_to_shared(smem);
    const unsigned mbar   = (unsigned)__cvta_generic_to_shared(&s_mbar);
    int bphase = 0;                  // mbarrier phase parity (all threads in lockstep)

    // ldmatrix per-thread address components (byte offsets from smem base)
    const int lr = lane & 7;
    const int g  = lane >> 3;
    const int l15r = lane & 7;                    // for x2: row uses lane&7 of low 16
    const int l15g = (lane >> 3) & 1;             // for x2: k-half select
    const unsigned aoff =
        (unsigned)((((wm << 4) + lr + ((g & 1) << 3)) * RSTRIDE + ((g >> 1) << 3)) * 2);
    const unsigned b01off =
        (unsigned)((RA_ROWS * RSTRIDE
                    + (((g >> 1) << 4) + (wn << 3) + lr) * RSTRIDE + ((g & 1) << 3)) * 2);
    const unsigned b2off =
        (unsigned)((RA_ROWS * RSTRIDE
                    + (32 + (wn << 3) + l15r) * RSTRIDE + (l15g << 3)) * 2);

    __shared__ unsigned s_sense;
    if (tid == 0) {
        s_sense = g_bar_sense;
        mbar_init(mbar, 1);
    }
    __syncthreads();

    auto gsync = [&]() {
        __syncthreads();
        if (tid == 0) {
            unsigned ls = s_sense ^ 1u;
            s_sense = ls;
            __threadfence();
            if (atomicAdd(&g_bar_count, 1u) == RBLK - 1) {
                atomicExch(&g_bar_count, 0u);
                __threadfence();
                g_bar_sense = ls;
            } else {
                while (g_bar_sense != ls) __nanosleep(32);
            }
        }
        __syncthreads();
    };

    // MMA over one quarter (16 k-chunks of 16) via ldmatrix: 3 gate accumulators.
    auto mmq = [&](int q, float* aR, float* aZ, float* aN) {
        const unsigned qb = smem_b + (unsigned)(q << 9);   // q*16 kk * 32B
#pragma unroll
        for (int kk2 = 0; kk2 < 16; kk2++) {
            const unsigned kb = kk2 * 32;
            unsigned af[4];
            ldsm_x4(af[0], af[1], af[2], af[3], qb + aoff + kb);
            unsigned brz[4];
            ldsm_x4(brz[0], brz[1], brz[2], brz[3], qb + b01off + kb);
            unsigned bn2[2];
            ldsm_x2(bn2[0], bn2[1], qb + b2off + kb);
            { unsigned bb[2] = { brz[0], brz[1] }; mma16816(aR, af, bb); }
            { unsigned bb[2] = { brz[2], brz[3] }; mma16816(aZ, af, bb); }
            { unsigned bb[2] = { bn2[0], bn2[1] }; mma16816(aN, af, bb); }
        }
    };

    // full block: bulk-copy A (64 rows) + B (48 gate rows), wait, compute all 4 quarters.
    auto block_gemm = [&](const bf16* Asrc, const bf16* Bsrc, int ldb,
                          float* aR, float* aZ, float* aN) {
        if (tid == 0) mbar_expect_tx(mbar, BLK_BYTES);
        __syncthreads();   // expect_tx set AND all threads done reading previous block
        if (tid < RA_ROWS) {
            bulk_cp(smem_b + tid * (RSTRIDE * 2), Asrc + (size_t)tid * HDIM, 2048, mbar);
        } else if (tid < RA_ROWS + RB_ROWS) {
            int br = tid - RA_ROWS;
            int grow = (br >> 4) * HDIM + (cid << 4) + (br & 15);
            bulk_cp(smem_b + (RA_ROWS + br) * (RSTRIDE * 2),
                    Bsrc + (size_t)grow * ldb, 2048, mbar);
        }
        mbar_wait(mbar, (unsigned)bphase);
        bphase ^= 1;
        mmq(0, aR, aZ, aN);
        mmq(1, aR, aZ, aN);
        mmq(2, aR, aZ, aN);
        mmq(3, aR, aZ, aN);
    };

    // ---- zero initial state (fp32 + bf16 buffer 0) ----
    for (int i = cid * 256 + tid; i < BATCH * HDIM; i += RBLK * 256) {
        __stcg(h1 + i, 0.f);
        __stcg(h2 + i, 0.f);
        __stcg((unsigned short*)h1bb + i, (unsigned short)0);
        __stcg((unsigned short*)h2bb + i, (unsigned short)0);
    }
    gsync();

    for (int t = 0; t < NSTEPS; t++) {
        const bool enc = (t < T_VID);
        const int p = t & 1;
        const bf16* h1r = h1bb + (size_t)p       * BATCH * HDIM;   // read buffer
        bf16*       h1w = h1bb + (size_t)(p ^ 1) * BATCH * HDIM;   // write buffer
        const bf16* h2r = h2bb + (size_t)p       * BATCH * HDIM;
        bf16*       h2w = h2bb + (size_t)(p ^ 1) * BATCH * HDIM;

        // ---- block 1: gh1 = h1r @ Whh1^T ----
        float aR1[4] = {0,0,0,0}, aZ1[4] = {0,0,0,0}, aN1[4] = {0,0,0,0};
        block_gemm(h1r, Whh1, HDIM, aR1, aZ1, aN1);

        // ---- gate1 epilogue -> h1 (fp32), h1w (bf16) ----
        {
            const float* git = enc ? (GI1 + (size_t)t * BATCH * G3) : bih1;
            const int gstride = enc ? G3 : 0;
#pragma unroll
            for (int pp = 0; pp < 2; pp++) {
#pragma unroll
                for (int q = 0; q < 2; q++) {
                    int row = (wm << 4) + (lane >> 2) + (pp << 3);
                    int j = (cid << 4) + (wn << 3) + ((lane & 3) << 1) + q;
                    int idx = (pp << 1) + q;
                    const float* gp = git + (size_t)row * gstride;
                    float rr = sigmf(gp[j]          + aR1[idx] + __ldg(bhh1 + j));
                    float zz = sigmf(gp[j + HDIM]   + aZ1[idx] + __ldg(bhh1 + j + HDIM));
                    float nn = tanhf(gp[j + 2*HDIM] + rr * (aN1[idx] + __ldg(bhh1 + j + 2*HDIM)));
                    int o = row * HDIM + j;
                    float hv = (1.f - zz) * nn + zz * __ldcg(h1 + o);
                    __stcg(h1 + o, hv);
                    __stcg((unsigned short*)h1w + o,
                           __bfloat16_as_ushort(__float2bfloat16(hv)));
                }
            }
        }

        // ---- block 2: gh2 = h2r @ Whh2^T (independent of gate1; pre-barrier) ----
        float aR2[4] = {0,0,0,0}, aZ2[4] = {0,0,0,0}, aNh[4] = {0,0,0,0};
        block_gemm(h2r, Whh2, HDIM, aR2, aZ2, aNh);
        gsync();   // all h1w writes complete chip-wide

        // ---- block 3: gi2 = h1w @ Wih2[:, :H]^T ----
        float aRi[4] = {0,0,0,0}, aZi[4] = {0,0,0,0}, aNi[4] = {0,0,0,0};
        block_gemm(h1w, Wih2, HDIM + WDIM, aRi, aZi, aNi);

        // ---- gate2 epilogue (combines block 2 + block 3 accumulators) ----
        {
            const int td = t - T_VID;
            bf16* h2save = enc ? nullptr : (H2all + (size_t)td * BATCH * HDIM);
#pragma unroll
            for (int pp = 0; pp < 2; pp++) {
#pragma unroll
                for (int q = 0; q < 2; q++) {
                    int row = (wm << 4) + (lane >> 2) + (pp << 3);
                    int j = (cid << 4) + (wn << 3) + ((lane & 3) << 1) + q;
                    int idx = (pp << 1) + q;
                    float wr = 0.f, wz = 0.f, wn_ = 0.f;
                    if (!enc) {
                        const float* w = GI2w + ((size_t)td * BATCH + row) * G3;
                        wr  = __ldcg(w + j);
                        wz  = __ldcg(w + j + HDIM);
                        wn_ = __ldcg(w + j + 2*HDIM);
                    }
                    float rr = sigmf(aRi[idx] + aR2[idx] + __ldg(bih2 + j) + __ldg(bhh2 + j) + wr);
                    float zz = sigmf(aZi[idx] + aZ2[idx] + __ldg(bih2 + j + HDIM) + __ldg(bhh2 + j + HDIM) + wz);
                    float nn = tanhf(aNi[idx] + __ldg(bih2 + j + 2*HDIM) + wn_
                                     + rr * (aNh[idx] + __ldg(bhh2 + j + 2*HDIM)));
                    int o = row * HDIM + j;
                    float hv = (1.f - zz) * nn + zz * __ldcg(h2 + o);
                    __stcg(h2 + o, hv);
                    unsigned short us = __bfloat16_as_ushort(__float2bfloat16(hv));
                    __stcg((unsigned short*)h2w + o, us);
                    if (h2save) __stcg((unsigned short*)h2save + o, us);
                }
            }
        }
        gsync();
    }
}

// ---------------- fused prep: 5 weight conversions + vid permute + word gather ----------------
#define CN1 ((long)G3*D_VID/2)
#define CN2 ((long)G3*HDIM/2)
#define CN3 ((long)G3*(HDIM+WDIM)/2)
#define CN4 ((long)G3*HDIM/2)
#define CN5 ((long)VOCAB*HDIM/2)
#define CNW (CN1+CN2+CN3+CN4+CN5)
#define PN_VID ((long)T_VID*BATCH*(D_VID/2))
#define PN_WRD ((long)MROWS*(WDIM/2))
__global__ void prep_kernel(const float* __restrict__ a1, bf16* o1,
                            const float* __restrict__ a2, bf16* o2,
                            const float* __restrict__ a3, bf16* o3,
                            const float* __restrict__ a4, bf16* o4,
                            const float* __restrict__ a5, bf16* o5,
                            const float* __restrict__ vid, bf16* __restrict__ vout,
                            const int* __restrict__ tgt, const float* __restrict__ emb,
                            bf16* __restrict__ wout)
{
    const long total = CNW + PN_VID + PN_WRD;
    long i = blockIdx.x * 256L + threadIdx.x;
    long stride = (long)gridDim.x * 256;
    for (; i < total; i += stride) {
        if (i < CNW) {
            const float2* src; __nv_bfloat162* dst; long j = i;
            if (j < CN1) { src = (const float2*)a1; dst = (__nv_bfloat162*)o1; }
            else if ((j -= CN1) < CN2) { src = (const float2*)a2; dst = (__nv_bfloat162*)o2; }
            else if ((j -= CN2) < CN3) { src = (const float2*)a3; dst = (__nv_bfloat162*)o3; }
            else if ((j -= CN3) < CN4) { src = (const float2*)a4; dst = (__nv_bfloat162*)o4; }
            else { j -= CN4; src = (const float2*)a5; dst = (__nv_bfloat162*)o5; }
            dst[j] = __float22bfloat162_rn(src[j]);
        } else if (i < CNW + PN_VID) {
            long k = i - CNW;
            long d2 = k & (D_VID/2 - 1);
            long tb = k >> 10;
            long b = tb & 63, t = tb >> 6;
            float2 v = ((const float2*)vid)[((b * T_VID + t) << 10) + d2];
            ((__nv_bfloat162*)vout)[k] = __float22bfloat162_rn(v);
        } else {
            long k = i - CNW - PN_VID;
            long j2 = k & (WDIM/2 - 1);
            long tb = k >> 8;
            long b = tb & 63, t = tb >> 6;
            int tok = tgt[b * MAXLEN + t];
            float2 v = ((const float2*)emb)[(long)tok * (WDIM/2) + j2];
            ((__nv_bfloat162*)wout)[k] = __float22bfloat162_rn(v);
        }
    }
}

// ---------------- online 2-pass log_softmax (rows of 32000 fp32) ----------------
__global__ void logsoftmax_kernel(float* __restrict__ data) {
    const int n4 = VOCAB / 4;
    float* row = data + (size_t)blockIdx.x * VOCAB;
    float4* r4 = (float4*)row;
    const int tid = threadIdx.x;
    const int lane = tid & 31, warp = tid >> 5;
    __shared__ float sm[8], ss[8];

    float m = -3.4e38f, s = 0.f;
    for (int i = tid; i < n4; i += 256) {
        float4 v = r4[i];
        float vv[4] = {v.x, v.y, v.z, v.w};
#pragma unroll
        for (int k = 0; k < 4; k++) {
            float x = vv[k];
            if (x > m) { s = s * __expf(m - x) + 1.f; m = x; }
            else         s += __expf(x - m);
        }
    }
#pragma unroll
    for (int o = 16; o; o >>= 1) {
        float om = __shfl_xor_sync(~0u, m, o);
        float os = __shfl_xor_sync(~0u, s, o);
        float nm = fmaxf(m, om);
        s = s * __expf(m - nm) + os * __expf(om - nm);
        m = nm;
    }
    if (lane == 0) { sm[warp] = m; ss[warp] = s; }
    __syncthreads();
    float M = sm[0], S = ss[0];
#pragma unroll
    for (int k = 1; k < 8; k++) {
        float nm = fmaxf(M, sm[k]);
        S = S * __expf(M - nm) + ss[k] * __expf(sm[k] - nm);
        M = nm;
    }
    float lse = M + logf(S);

    for (int i = tid; i < n4; i += 256) {
        float4 v = r4[i];
        v.x -= lse; v.y -= lse; v.z -= lse; v.w -= lse;
        r4[i] = v;
    }
}

// ---------------- launcher ----------------
extern "C" void kernel_launch(void* const* d_in, const int* in_sizes, int n_in,
                              void* d_out, int out_size)
{
    const float* vid  = (const float*)d_in[0];
    const int*   tgt  = (const int*)  d_in[1];
    const float* emb  = (const float*)d_in[2];
    const float* Wih1 = (const float*)d_in[3];
    const float* Whh1 = (const float*)d_in[4];
    const float* bih1 = (const float*)d_in[5];
    const float* bhh1 = (const float*)d_in[6];
    const float* Wih2 = (const float*)d_in[7];
    const float* Whh2 = (const float*)d_in[8];
    const float* bih2 = (const float*)d_in[9];
    const float* bhh2 = (const float*)d_in[10];
    const float* Wout = (const float*)d_in[11];
    const float* bout = (const float*)d_in[12];
    float* out = (float*)d_out;

    cudaFuncSetAttribute(gemm_kernel<256>, cudaFuncAttributeMaxDynamicSharedMemorySize, SM_G256);
    cudaFuncSetAttribute(recurrence_kernel, cudaFuncAttributeMaxDynamicSharedMemorySize, SM_REC);

    bf16 *pWih1, *pWhh1, *pWih2, *pWhh2, *pWout, *pVid, *pWords, *ph1b, *ph2b, *pH2all;
    float *pGI1, *pGI2w, *ph1, *ph2;
    cudaGetSymbolAddress((void**)&pWih1, g_Wih1);
    cudaGetSymbolAddress((void**)&pWhh1, g_Whh1);
    cudaGetSymbolAddress((void**)&pWih2, g_Wih2);
    cudaGetSymbolAddress((void**)&pWhh2, g_Whh2);
    cudaGetSymbolAddress((void**)&pWout, g_Wout);
    cudaGetSymbolAddress((void**)&pVid,  g_vid);
    cudaGetSymbolAddress((void**)&pWords,g_words);
    cudaGetSymbolAddress((void**)&pGI1,  g_GI1);
    cudaGetSymbolAddress((void**)&pGI2w, g_GI2w);
    cudaGetSymbolAddress((void**)&ph1,   g_h1);
    cudaGetSymbolAddress((void**)&ph2,   g_h2);
    cudaGetSymbolAddress((void**)&ph1b,  g_h1b);
    cudaGetSymbolAddress((void**)&ph2b,  g_h2b);
    cudaGetSymbolAddress((void**)&pH2all,g_H2all);

    // 0: fused prep (weight conversions + vid permute + word gather)
    prep_kernel<<<2048, 256>>>(Wih1, pWih1, Whh1, pWhh1, Wih2, pWih2,
                               Whh2, pWhh2, Wout, pWout,
                               vid, pVid, tgt, emb, pWords);

    // 1: GI1 = vid @ W_ih1^T + b_ih1   (2560 x 3072 x 2048)
    gemm_kernel<256><<<dim3(G3/256, (T_VID*BATCH)/64), 256, SM_G256>>>(
        pVid, D_VID, pWih1, D_VID, pGI1, G3, bih1, D_VID, 0);
    // 2: GI2w = words @ W_ih2[:,H:]^T  (1728 x 3072 x 512), no bias
    gemm_kernel<256><<<dim3(G3/256, MROWS/64), 256, SM_G256>>>(
        pWords, WDIM, pWih2 + HDIM, HDIM+WDIM, pGI2w, G3, nullptr, WDIM, 0);

    // 3: persistent recurrence (all 67 steps, R13 bulk loader + ldmatrix mmq)
    recurrence_kernel<<<RBLK, 256, SM_REC>>>(
        pWhh1, pWih2, pWhh2,
        bih1, bhh1, bih2, bhh2,
        pGI1, pGI2w,
        ph1, ph2, ph1b, ph2b, pH2all);

    // 4: logits (1728 x 32000 x 1024), permuted into d_out
    gemm_kernel<256><<<dim3(VOCAB/256, MROWS/64), 256, SM_G256>>>(
        pH2all, HDIM, pWout, HDIM, out, VOCAB, bout, HDIM, 1);

    // 5: online log_softmax
    logsoftmax_kernel<<<DECSTEPS*BATCH, 256>>>(out);
}